// round 12
// baseline (speedup 1.0000x reference)
#include <cuda_runtime.h>
#include <cuda_bf16.h>
#include <cstdint>

#define LLEN 32768
#define NN 2048
#define DD 64
#define HH 256
#define KIN 205
#define MT 64                    // tokens per CTA (M)
#define NTHR 256
#define ASTRB 512                // A row stride bytes (256 bf16, XOR-swizzled)
#define A_BYTES (MT * ASTRB)     // 32768 per matrix
#define OFF_ALO A_BYTES
#define OFF_B   (2 * A_BYTES)    // 65536
#define BPAN 8192                // B panel bytes per matrix (256 rows x 32B, K=16)
#define BSTAGE (2 * BPAN)        // hi+lo per stage = 16384
#define SMEM_DYN (OFF_B + 3 * BSTAGE)   // 114688 -> 2 CTAs/SM

struct Sizes { int c, outN; };

// ---- device scratch: transposed bf16 hi/lo weights  B[l][n][k] --------------
__device__ __nv_bfloat16 g_Bhi[4][HH * HH];
__device__ __nv_bfloat16 g_Blo[4][HH * HH];

// ---- helpers ----------------------------------------------------------------
__device__ __forceinline__ uint32_t smem_u32(const void* p) {
    uint32_t a;
    asm("{ .reg .u64 t; cvta.to.shared.u64 t, %1; cvt.u32.u64 %0, t; }"
        : "=r"(a) : "l"(p));
    return a;
}
__device__ __forceinline__ void ldsm4(uint32_t* r, uint32_t a) {
    asm volatile("ldmatrix.sync.aligned.m8n8.x4.shared.b16 {%0,%1,%2,%3}, [%4];"
                 : "=r"(r[0]), "=r"(r[1]), "=r"(r[2]), "=r"(r[3]) : "r"(a));
}
__device__ __forceinline__ void ldsm2(uint32_t* r, uint32_t a) {
    asm volatile("ldmatrix.sync.aligned.m8n8.x2.shared.b16 {%0,%1}, [%2];"
                 : "=r"(r[0]), "=r"(r[1]) : "r"(a));
}
__device__ __forceinline__ void mmabf(float* c, const uint32_t* a, const uint32_t* b) {
    asm volatile("mma.sync.aligned.m16n8k16.row.col.f32.bf16.bf16.f32 "
                 "{%0,%1,%2,%3}, {%4,%5,%6,%7}, {%8,%9}, {%0,%1,%2,%3};"
                 : "+f"(c[0]), "+f"(c[1]), "+f"(c[2]), "+f"(c[3])
                 : "r"(a[0]), "r"(a[1]), "r"(a[2]), "r"(a[3]),
                   "r"(b[0]), "r"(b[1]));
}
__device__ __forceinline__ uint32_t pack_bf2(float x, float y) {
    __nv_bfloat16 hx = __float2bfloat16(x), hy = __float2bfloat16(y);
    return (uint32_t)__bfloat16_as_ushort(hx)
         | ((uint32_t)__bfloat16_as_ushort(hy) << 16);
}
__device__ __forceinline__ void cp16(uint32_t dst, const void* src) {
    asm volatile("cp.async.cg.shared.global [%0], [%1], 16;"
                 :: "r"(dst), "l"(src));
}
// swizzled A element byte offset (2B elements, 512B rows, 16B-chunk XOR row&7)
__device__ __forceinline__ uint32_t a_off(int m, int ch) {
    return (uint32_t)(m * ASTRB + (((ch >> 3) ^ (m & 7)) << 4) + ((ch & 7) << 1));
}

// panel p (K rows [16p,16p+16)) of layer weights -> stage st; 256 threads
// B rows are 32B (2 chunks): naturally conflict-free for ldsm2 and stores.
__device__ __forceinline__ void issue_panel(uint32_t bBU, int st,
                                            const __nv_bfloat16* gh,
                                            const __nv_bfloat16* gl,
                                            int p, int t)
{
#pragma unroll
    for (int q4 = 0; q4 < 4; ++q4) {
        int c  = q4 * 256 + t;                 // 0..1023 chunks of 16B
        int mm = c >> 9;                       // 0:hi 1:lo
        int idx = c & 511;
        int n = idx >> 1, q = idx & 1;
        const __nv_bfloat16* src = (mm ? gl : gh) + n * HH + p * 16 + q * 8;
        uint32_t dst = bBU + (uint32_t)(st * BSTAGE + mm * BPAN + n * 32 + q * 16);
        cp16(dst, src);
    }
    asm volatile("cp.async.commit_group;" ::: "memory");
}

// ---- prep: transpose + bf16 hi/lo split of layer weights --------------------
__global__ void prep_kernel(const float* __restrict__ W0, const float* __restrict__ W1,
                            const float* __restrict__ W2, const float* __restrict__ W3)
{
    int n = blockIdx.x;              // output channel
    int l = blockIdx.y;              // layer
    int k = threadIdx.x;             // input channel
    const float* W = (l == 0) ? W0 : (l == 1) ? W1 : (l == 2) ? W2 : W3;
    float v = 0.f;
    if (l != 0 || k < KIN) v = __ldg(W + k * HH + n);
    __nv_bfloat16 hi = __float2bfloat16(v);
    g_Bhi[l][n * HH + k] = hi;
    g_Blo[l][n * HH + k] = __float2bfloat16(v - __bfloat162float(hi));
}

// ---- main fused kernel ------------------------------------------------------
__global__ void __launch_bounds__(NTHR, 2)
lisa_mma(const float* __restrict__ coord, const float* __restrict__ latent,
         const float* __restrict__ b0, const float* __restrict__ b1,
         const float* __restrict__ b2, const float* __restrict__ b3,
         const float* __restrict__ W4, const float* __restrict__ b4,
         float* __restrict__ out, Sizes sz)
{
    extern __shared__ char sm[];
    const uint32_t sm0 = smem_u32(sm);
    const uint32_t aHiU = sm0, bBU = sm0 + OFF_B;

    const int t = threadIdx.x, wid = t >> 5, lane = t & 31;
    const int nw = wid;                      // N-slice warp (32 cols each)
    const int tok0 = blockIdx.x * MT;
    const int bb = tok0 / LLEN;
    const float* lat = latent + bb * NN * DD;

    // prefetch layer-0 panels 0,1 (overlaps the feature build below)
    issue_panel(bBU, 0, g_Bhi[0], g_Blo[0], 0, t);
    issue_panel(bBU, 1, g_Bhi[0], g_Blo[0], 1, t);

    // ---- feature build: coord | PE(12) | sampled(192) | zeros, bf16 hi/lo ---
#pragma unroll 1
    for (int tt = 0; tt < 8; ++tt) {
        int m = wid * 8 + tt;                // 8 warps x 8 = 64 tokens
        float c = __ldg(coord + min(tok0 + m, sz.c - 1));
        float ix = c * (float)NN - 0.5f;
        float x0f = floorf(ix);
        float fr = ix - x0f, om = 1.f - fr;
        int x0 = (int)x0f;
        int i0 = min(max(x0, 0), NN - 1);
        int i1 = min(max(x0 + 1, 0), NN - 1);
#pragma unroll
        for (int r = 0; r < 8; ++r) {
            int ch = r * 32 + lane;
            float v = 0.f;
            if (ch == 0) v = c;
            else if (ch < 13) {
                int k = ch - 1;
                float ang = c * (float)(1 << (k >> 1));
                v = (k & 1) ? cosf(ang) : sinf(ang);
            } else if (ch < 205) {
                int u = ch - 13, s = u >> 6, d = u & 63;
                int j0 = min(max(i0 + s - 1, 0), NN - 1);
                int j1 = min(max(i1 + s - 1, 0), NN - 1);
                v = om * __ldg(lat + j0 * DD + d) + fr * __ldg(lat + j1 * DD + d);
            }
            __nv_bfloat16 h = __float2bfloat16(v);
            uint32_t o = a_off(m, ch);
            *reinterpret_cast<__nv_bfloat16*>(sm + o)           = h;
            *reinterpret_cast<__nv_bfloat16*>(sm + OFF_ALO + o) =
                __float2bfloat16(v - __bfloat162float(h));
        }
    }

    const float* bgs[4] = { b0, b1, b2, b3 };

#pragma unroll 1
    for (int l = 0; l < 4; ++l) {
        const int nP = (l == 0) ? 13 : 16;   // layer0 K=208 (>=205), K16 panels

        float C[4][4][4];
#pragma unroll
        for (int a = 0; a < 4; ++a)
#pragma unroll
            for (int b = 0; b < 4; ++b)
#pragma unroll
                for (int q = 0; q < 4; ++q) C[a][b][q] = 0.f;

#pragma unroll 1
        for (int p = 0; p < nP; ++p) {
            if (p + 1 < nP) {
                asm volatile("cp.async.wait_group 1;" ::: "memory");
            } else {
                asm volatile("cp.async.wait_group 0;" ::: "memory");
            }
            __syncthreads();     // panel p visible; stage (p+2)%3 free; A ordered

            if (p + 2 < nP)
                issue_panel(bBU, (p + 2) % 3, g_Bhi[l], g_Blo[l], p + 2, t);

            const uint32_t bU = bBU + (uint32_t)((p % 3) * BSTAGE);
            uint32_t bh[4][2], bl[4][2];
#pragma unroll
            for (int nt = 0; nt < 4; ++nt) {
                int row = nw * 32 + nt * 8 + (lane & 7);
                uint32_t rowb = bU + (uint32_t)(row * 32 + ((lane >> 3) & 1) * 16);
                ldsm2(bh[nt], rowb);
                ldsm2(bl[nt], rowb + BPAN);
            }
#pragma unroll
            for (int mt = 0; mt < 4; ++mt) {
                uint32_t ah[4], al[4];
                int row = mt * 16 + (lane & 15);
                int chk = p * 2 + (lane >> 4);
                uint32_t ra = aHiU + (uint32_t)(row * ASTRB + ((chk ^ (row & 7)) << 4));
                ldsm4(ah, ra);
                ldsm4(al, ra + OFF_ALO);
                // chain-broken order: each C gets links >=4 apart
#pragma unroll
                for (int nt = 0; nt < 4; ++nt) mmabf(C[mt][nt], ah, bh[nt]);
#pragma unroll
                for (int nt = 0; nt < 4; ++nt) mmabf(C[mt][nt], ah, bl[nt]);
#pragma unroll
                for (int nt = 0; nt < 4; ++nt) mmabf(C[mt][nt], al, bh[nt]);
            }
        }
        __syncthreads();         // all compute done: A writable, B stages free

        if (l < 3) {             // prefetch next layer's first panels over epilogue
            issue_panel(bBU, 0, g_Bhi[l + 1], g_Blo[l + 1], 0, t);
            issue_panel(bBU, 1, g_Bhi[l + 1], g_Blo[l + 1], 1, t);
        }

        const float* bg = bgs[l];
        if (l < 3) {
            // bias + relu + re-split into A (k-layout for next layer)
#pragma unroll
            for (int nt = 0; nt < 4; ++nt) {
                int n0 = nw * 32 + nt * 8 + (lane & 3) * 2;
                float bi0 = __ldg(bg + n0), bi1 = __ldg(bg + n0 + 1);
#pragma unroll
                for (int mt = 0; mt < 4; ++mt) {
                    int m0 = mt * 16 + (lane >> 2);
                    float v0 = fmaxf(C[mt][nt][0] + bi0, 0.f);
                    float v1 = fmaxf(C[mt][nt][1] + bi1, 0.f);
                    float v2 = fmaxf(C[mt][nt][2] + bi0, 0.f);
                    float v3 = fmaxf(C[mt][nt][3] + bi1, 0.f);
                    uint32_t h01 = pack_bf2(v0, v1), h23 = pack_bf2(v2, v3);
                    float r0 = v0 - __bfloat162float(__ushort_as_bfloat16((unsigned short)h01));
                    float r1 = v1 - __bfloat162float(__ushort_as_bfloat16((unsigned short)(h01 >> 16)));
                    float r2 = v2 - __bfloat162float(__ushort_as_bfloat16((unsigned short)h23));
                    float r3 = v3 - __bfloat162float(__ushort_as_bfloat16((unsigned short)(h23 >> 16)));
                    uint32_t oA = a_off(m0, n0), oB = a_off(m0 + 8, n0);
                    *reinterpret_cast<uint32_t*>(sm + oA)           = h01;
                    *reinterpret_cast<uint32_t*>(sm + OFF_ALO + oA) = pack_bf2(r0, r1);
                    *reinterpret_cast<uint32_t*>(sm + oB)           = h23;
                    *reinterpret_cast<uint32_t*>(sm + OFF_ALO + oB) = pack_bf2(r2, r3);
                }
            }
            // next layer's iter-0 sync orders these writes before ldmatrix
        } else {
            // final: bias+relu, dot with W4, reduce 256->1 per token
            float slo[4] = {0.f, 0.f, 0.f, 0.f}, shi[4] = {0.f, 0.f, 0.f, 0.f};
#pragma unroll
            for (int nt = 0; nt < 4; ++nt) {
                int n0 = nw * 32 + nt * 8 + (lane & 3) * 2;
                float bi0 = __ldg(bg + n0), bi1 = __ldg(bg + n0 + 1);
                float w0 = __ldg(W4 + n0), w1 = __ldg(W4 + n0 + 1);
#pragma unroll
                for (int mt = 0; mt < 4; ++mt) {
                    slo[mt] += fmaxf(C[mt][nt][0] + bi0, 0.f) * w0
                             + fmaxf(C[mt][nt][1] + bi1, 0.f) * w1;
                    shi[mt] += fmaxf(C[mt][nt][2] + bi0, 0.f) * w0
                             + fmaxf(C[mt][nt][3] + bi1, 0.f) * w1;
                }
            }
#pragma unroll
            for (int mt = 0; mt < 4; ++mt) {
                slo[mt] += __shfl_xor_sync(0xffffffffu, slo[mt], 1);
                slo[mt] += __shfl_xor_sync(0xffffffffu, slo[mt], 2);
                shi[mt] += __shfl_xor_sync(0xffffffffu, shi[mt], 1);
                shi[mt] += __shfl_xor_sync(0xffffffffu, shi[mt], 2);
            }
            float* red = reinterpret_cast<float*>(sm + OFF_B);   // 64 x 8 floats
            if ((lane & 3) == 0) {
                int g = lane >> 2;
#pragma unroll
                for (int mt = 0; mt < 4; ++mt) {
                    int m0 = mt * 16 + g;
                    red[m0 * 8 + nw]       = slo[mt];
                    red[(m0 + 8) * 8 + nw] = shi[mt];
                }
            }
            __syncthreads();
            if (t < MT) {
                float r = __ldg(b4);
#pragma unroll
                for (int ww = 0; ww < 8; ++ww) r += red[t * 8 + ww];
                if (tok0 + t < sz.outN) out[tok0 + t] = r;
            }
        }
    }
}

// ---- size-based input resolution (elements OR bytes; any ordering) ----------
extern "C" void kernel_launch(void* const* d_in, const int* in_sizes, int n_in,
                              void* d_out, int out_size) {
    long long es[64];
    int m = n_in > 64 ? 64 : n_in;
    bool bytemode = false;
    for (int i = 0; i < m; ++i) if (in_sizes[i] == 4194304) bytemode = true;
    for (int i = 0; i < m; ++i)
        es[i] = bytemode ? (long long)in_sizes[i] / 4 : (long long)in_sizes[i];
    long long outN = bytemode ? (long long)out_size / 4 : (long long)out_size;

    int iCoord = -1, iLat = -1, iW0 = -1, iB4 = -1;
    int idx65[3];  int n65 = 0;
    int idx256[5]; int n256 = 0;
    for (int i = 0; i < m; ++i) {
        long long s = es[i];
        if      (s == 262144)  iCoord = i;
        else if (s == 1048576) iLat   = i;
        else if (s == 52480)   iW0    = i;
        else if (s == 1)       iB4    = i;
        else if (s == 65536 && n65 < 3)  idx65[n65++]  = i;
        else if (s == 256   && n256 < 5) idx256[n256++] = i;
    }

    int iW1, iW2, iW3, iW4, iB0, iB1, iB2, iB3;
    if (n65 == 3 && n256 == 5 && iCoord >= 0 && iLat >= 0 && iW0 >= 0 && iB4 >= 0) {
        iW1 = idx65[0]; iW2 = idx65[1]; iW3 = idx65[2];
        if (idx256[0] < idx65[0]) {     // biases interleaved (declaration order)
            iB0 = idx256[0]; iB1 = idx256[1]; iB2 = idx256[2];
            iB3 = idx256[3]; iW4 = idx256[4];
        } else {                        // W-block first (sorted order)
            iW4 = idx256[0]; iB0 = idx256[1]; iB1 = idx256[2];
            iB2 = idx256[3]; iB3 = idx256[4];
        }
    } else {
        iCoord = 0 % m;  iLat = 1 % m;  iW0 = 2 % m;  iB0 = 3 % m;
        iW1 = 4 % m;     iB1 = 5 % m;   iW2 = 6 % m;  iB2 = 7 % m;
        iW3 = 8 % m;     iB3 = 9 % m;   iW4 = 10 % m; iB4 = 11 % m;
    }

    Sizes sz;
    sz.c = (int)es[iCoord]; sz.outN = (int)outN;

    const float* coord  = (const float*)d_in[iCoord];
    const float* latent = (const float*)d_in[iLat];
    const float* W0 = (const float*)d_in[iW0]; const float* b0 = (const float*)d_in[iB0];
    const float* W1 = (const float*)d_in[iW1]; const float* b1 = (const float*)d_in[iB1];
    const float* W2 = (const float*)d_in[iW2]; const float* b2 = (const float*)d_in[iB2];
    const float* W3 = (const float*)d_in[iW3]; const float* b3 = (const float*)d_in[iB3];
    const float* W4 = (const float*)d_in[iW4]; const float* b4 = (const float*)d_in[iB4];

    prep_kernel<<<dim3(HH, 4), HH>>>(W0, W1, W2, W3);

    cudaFuncSetAttribute(lisa_mma, cudaFuncAttributeMaxDynamicSharedMemorySize,
                         SMEM_DYN);
    int blocks = (int)((outN + MT - 1) / MT);    // 4096 expected
    lisa_mma<<<blocks, NTHR, SMEM_DYN>>>(coord, latent, b0, b1, b2, b3, W4, b4,
                                         (float*)d_out, sz);
}

// round 13
// speedup vs baseline: 1.5072x; 1.5072x over previous
#include <cuda_runtime.h>
#include <cuda_fp16.h>
#include <cstdint>

#define LLEN 32768
#define NN 2048
#define DD 64
#define HH 256
#define KIN 205
#define MT 128                   // tokens per CTA (M)
#define NTHR 512
#define ASTRB 512                // A row stride bytes (256 fp16, XOR-swizzled)
#define A_BYTES (MT * ASTRB)     // 65536 per matrix
#define OFF_ALO A_BYTES
#define OFF_B   (2 * A_BYTES)    // 131072
#define BSTAGE 16384             // B stage bytes (256 rows x 64B, K=32, single fp16)
#define SMEM_DYN (OFF_B + 3 * BSTAGE)   // 180224 (1 CTA/SM)

struct Sizes { int c, outN; };

// ---- device scratch: transposed fp16 weights  B[l][n][k] --------------------
__device__ __half g_B16[4][HH * HH];

// ---- helpers ----------------------------------------------------------------
__device__ __forceinline__ uint32_t smem_u32(const void* p) {
    uint32_t a;
    asm("{ .reg .u64 t; cvta.to.shared.u64 t, %1; cvt.u32.u64 %0, t; }"
        : "=r"(a) : "l"(p));
    return a;
}
__device__ __forceinline__ void ldsm4(uint32_t* r, uint32_t a) {
    asm volatile("ldmatrix.sync.aligned.m8n8.x4.shared.b16 {%0,%1,%2,%3}, [%4];"
                 : "=r"(r[0]), "=r"(r[1]), "=r"(r[2]), "=r"(r[3]) : "r"(a));
}
__device__ __forceinline__ void ldsm2(uint32_t* r, uint32_t a) {
    asm volatile("ldmatrix.sync.aligned.m8n8.x2.shared.b16 {%0,%1}, [%2];"
                 : "=r"(r[0]), "=r"(r[1]) : "r"(a));
}
__device__ __forceinline__ void mmah(float* c, const uint32_t* a, const uint32_t* b) {
    asm volatile("mma.sync.aligned.m16n8k16.row.col.f32.f16.f16.f32 "
                 "{%0,%1,%2,%3}, {%4,%5,%6,%7}, {%8,%9}, {%0,%1,%2,%3};"
                 : "+f"(c[0]), "+f"(c[1]), "+f"(c[2]), "+f"(c[3])
                 : "r"(a[0]), "r"(a[1]), "r"(a[2]), "r"(a[3]),
                   "r"(b[0]), "r"(b[1]));
}
__device__ __forceinline__ uint32_t pack_h2(float x, float y) {
    __half hx = __float2half(x), hy = __float2half(y);
    return (uint32_t)__half_as_ushort(hx)
         | ((uint32_t)__half_as_ushort(hy) << 16);
}
__device__ __forceinline__ void cp16(uint32_t dst, const void* src) {
    asm volatile("cp.async.cg.shared.global [%0], [%1], 16;"
                 :: "r"(dst), "l"(src));
}
// swizzled A element byte offset (2B elements, 512B rows, 16B-chunk XOR row&7)
__device__ __forceinline__ uint32_t a_off(int m, int ch) {
    return (uint32_t)(m * ASTRB + (((ch >> 3) ^ (m & 7)) << 4) + ((ch & 7) << 1));
}

// panel p (K rows [32p,32p+32)) of layer weights -> stage st; all 512 threads
__device__ __forceinline__ void issue_panel(uint32_t bBU, int st,
                                            const __half* gw, int p, int t)
{
#pragma unroll
    for (int q4 = 0; q4 < 2; ++q4) {
        int c  = q4 * 512 + t;                 // 0..1023 chunks of 16B
        int n = c >> 2, q = c & 3;             // 4 chunks = 64B per row
        const __half* src = gw + n * HH + p * 32 + q * 8;
        uint32_t dst = bBU + (uint32_t)(st * BSTAGE + n * 64 + ((q ^ (n & 3)) << 4));
        cp16(dst, src);
    }
    asm volatile("cp.async.commit_group;" ::: "memory");
}

// ---- prep: transpose + fp16 round of layer weights --------------------------
__global__ void prep_kernel(const float* __restrict__ W0, const float* __restrict__ W1,
                            const float* __restrict__ W2, const float* __restrict__ W3)
{
    int n = blockIdx.x;              // output channel
    int l = blockIdx.y;              // layer
    int k = threadIdx.x;             // input channel
    const float* W = (l == 0) ? W0 : (l == 1) ? W1 : (l == 2) ? W2 : W3;
    float v = 0.f;
    if (l != 0 || k < KIN) v = __ldg(W + k * HH + n);
    g_B16[l][n * HH + k] = __float2half(v);
}

// ---- main fused kernel ------------------------------------------------------
__global__ void __launch_bounds__(NTHR, 1)
lisa_mma(const float* __restrict__ coord, const float* __restrict__ latent,
         const float* __restrict__ b0, const float* __restrict__ b1,
         const float* __restrict__ b2, const float* __restrict__ b3,
         const float* __restrict__ W4, const float* __restrict__ b4,
         float* __restrict__ out, Sizes sz)
{
    extern __shared__ char sm[];
    const uint32_t sm0 = smem_u32(sm);
    const uint32_t aHiU = sm0, bBU = sm0 + OFF_B;

    const int t = threadIdx.x, wid = t >> 5, lane = t & 31;
    const int mh = wid >> 3;                 // M-half 0/1 (64 tokens each)
    const int nw = wid & 7;                  // N-slice warp (32 cols)
    const int tok0 = blockIdx.x * MT;
    const int bb = tok0 / LLEN;
    const float* lat = latent + bb * NN * DD;

    // prefetch layer-0 panels 0,1 (overlaps the feature build below)
    issue_panel(bBU, 0, g_B16[0], 0, t);
    issue_panel(bBU, 1, g_B16[0], 1, t);

    // ---- feature build: coord | PE(12) | sampled(192) | zeros, fp16 hi/lo ---
#pragma unroll 2
    for (int tt = 0; tt < 8; ++tt) {
        int m = wid * 8 + tt;                // 16 warps x 8 = 128 tokens
        float c = __ldg(coord + min(tok0 + m, sz.c - 1));
        float ix = c * (float)NN - 0.5f;
        float x0f = floorf(ix);
        float fr = ix - x0f, om = 1.f - fr;
        int x0 = (int)x0f;
        int i0 = min(max(x0, 0), NN - 1);
        int i1 = min(max(x0 + 1, 0), NN - 1);
#pragma unroll
        for (int r = 0; r < 8; ++r) {
            int ch = r * 32 + lane;
            float v = 0.f;
            if (ch == 0) v = c;
            else if (ch < 13) {
                int k = ch - 1;
                float ang = c * (float)(1 << (k >> 1));
                v = (k & 1) ? cosf(ang) : sinf(ang);
            } else if (ch < 205) {
                int u = ch - 13, s = u >> 6, d = u & 63;
                int j0 = min(max(i0 + s - 1, 0), NN - 1);
                int j1 = min(max(i1 + s - 1, 0), NN - 1);
                v = om * __ldg(lat + j0 * DD + d) + fr * __ldg(lat + j1 * DD + d);
            }
            __half h = __float2half(v);
            uint32_t o = a_off(m, ch);
            *reinterpret_cast<__half*>(sm + o)           = h;
            *reinterpret_cast<__half*>(sm + OFF_ALO + o) =
                __float2half(v - __half2float(h));
        }
    }

    const float* bgs[4] = { b0, b1, b2, b3 };

#pragma unroll 1
    for (int l = 0; l < 4; ++l) {
        const int nP = (l == 0) ? 7 : 8;     // layer0 K=224 (205 + zero pad)

        float C[4][4][4];
#pragma unroll
        for (int a = 0; a < 4; ++a)
#pragma unroll
            for (int b = 0; b < 4; ++b)
#pragma unroll
                for (int q = 0; q < 4; ++q) C[a][b][q] = 0.f;

#pragma unroll 1
        for (int p = 0; p < nP; ++p) {
            if (p + 1 < nP) {
                asm volatile("cp.async.wait_group 1;" ::: "memory");
            } else {
                asm volatile("cp.async.wait_group 0;" ::: "memory");
            }
            __syncthreads();     // panel p visible; stage (p+2)%3 free; A ordered

            if (p + 2 < nP)
                issue_panel(bBU, (p + 2) % 3, g_B16[l], p + 2, t);

            const uint32_t bU = bBU + (uint32_t)((p % 3) * BSTAGE);
#pragma unroll
            for (int ks = 0; ks < 2; ++ks) {
                uint32_t bh[4][2];
#pragma unroll
                for (int nt = 0; nt < 4; ++nt) {
                    int row = nw * 32 + nt * 8 + (lane & 7);
                    int chk = 2 * ks + ((lane >> 3) & 1);
                    uint32_t rowb = bU + (uint32_t)(row * 64 + ((chk ^ (row & 3)) << 4));
                    ldsm2(bh[nt], rowb);
                }
#pragma unroll
                for (int mt = 0; mt < 4; ++mt) {
                    uint32_t ah[4], al[4];
                    int row = mh * 64 + mt * 16 + (lane & 15);
                    int chk = p * 4 + ks * 2 + (lane >> 4);
                    uint32_t ra = aHiU + (uint32_t)(row * ASTRB
                                                    + ((chk ^ (row & 7)) << 4));
                    ldsm4(ah, ra);
                    ldsm4(al, ra + OFF_ALO);
                    // chain-broken order: each C gets links >=4 apart
#pragma unroll
                    for (int nt = 0; nt < 4; ++nt) mmah(C[mt][nt], ah, bh[nt]);
#pragma unroll
                    for (int nt = 0; nt < 4; ++nt) mmah(C[mt][nt], al, bh[nt]);
                }
            }
        }
        __syncthreads();         // all compute done: A writable, B stages free

        if (l < 3) {             // prefetch next layer's first panels over epilogue
            issue_panel(bBU, 0, g_B16[l + 1], 0, t);
            issue_panel(bBU, 1, g_B16[l + 1], 1, t);
        }

        const float* bg = bgs[l];
        if (l < 3) {
            // bias + relu + re-split into A (k-layout for next layer)
#pragma unroll
            for (int nt = 0; nt < 4; ++nt) {
                int n0 = nw * 32 + nt * 8 + (lane & 3) * 2;
                float bi0 = __ldg(bg + n0), bi1 = __ldg(bg + n0 + 1);
#pragma unroll
                for (int mt = 0; mt < 4; ++mt) {
                    int m0 = mh * 64 + mt * 16 + (lane >> 2);
                    float v0 = fmaxf(C[mt][nt][0] + bi0, 0.f);
                    float v1 = fmaxf(C[mt][nt][1] + bi1, 0.f);
                    float v2 = fmaxf(C[mt][nt][2] + bi0, 0.f);
                    float v3 = fmaxf(C[mt][nt][3] + bi1, 0.f);
                    uint32_t h01 = pack_h2(v0, v1), h23 = pack_h2(v2, v3);
                    float r0 = v0 - __half2float(__ushort_as_half((unsigned short)h01));
                    float r1 = v1 - __half2float(__ushort_as_half((unsigned short)(h01 >> 16)));
                    float r2 = v2 - __half2float(__ushort_as_half((unsigned short)h23));
                    float r3 = v3 - __half2float(__ushort_as_half((unsigned short)(h23 >> 16)));
                    uint32_t oA = a_off(m0, n0), oB = a_off(m0 + 8, n0);
                    *reinterpret_cast<uint32_t*>(sm + oA)           = h01;
                    *reinterpret_cast<uint32_t*>(sm + OFF_ALO + oA) = pack_h2(r0, r1);
                    *reinterpret_cast<uint32_t*>(sm + oB)           = h23;
                    *reinterpret_cast<uint32_t*>(sm + OFF_ALO + oB) = pack_h2(r2, r3);
                }
            }
            // next layer's iter-0 sync orders these writes before ldmatrix
        } else {
            // final: bias+relu, dot with W4, reduce 256->1 per token
            float slo[4] = {0.f, 0.f, 0.f, 0.f}, shi[4] = {0.f, 0.f, 0.f, 0.f};
#pragma unroll
            for (int nt = 0; nt < 4; ++nt) {
                int n0 = nw * 32 + nt * 8 + (lane & 3) * 2;
                float bi0 = __ldg(bg + n0), bi1 = __ldg(bg + n0 + 1);
                float w0 = __ldg(W4 + n0), w1 = __ldg(W4 + n0 + 1);
#pragma unroll
                for (int mt = 0; mt < 4; ++mt) {
                    slo[mt] += fmaxf(C[mt][nt][0] + bi0, 0.f) * w0
                             + fmaxf(C[mt][nt][1] + bi1, 0.f) * w1;
                    shi[mt] += fmaxf(C[mt][nt][2] + bi0, 0.f) * w0
                             + fmaxf(C[mt][nt][3] + bi1, 0.f) * w1;
                }
            }
#pragma unroll
            for (int mt = 0; mt < 4; ++mt) {
                slo[mt] += __shfl_xor_sync(0xffffffffu, slo[mt], 1);
                slo[mt] += __shfl_xor_sync(0xffffffffu, slo[mt], 2);
                shi[mt] += __shfl_xor_sync(0xffffffffu, shi[mt], 1);
                shi[mt] += __shfl_xor_sync(0xffffffffu, shi[mt], 2);
            }
            float* red = reinterpret_cast<float*>(sm + OFF_B);   // 128 x 8 floats
            if ((lane & 3) == 0) {
                int g = lane >> 2;
#pragma unroll
                for (int mt = 0; mt < 4; ++mt) {
                    int m0 = mh * 64 + mt * 16 + g;
                    red[m0 * 8 + nw]       = slo[mt];
                    red[(m0 + 8) * 8 + nw] = shi[mt];
                }
            }
            __syncthreads();
            if (t < MT) {
                float r = __ldg(b4);
#pragma unroll
                for (int ww = 0; ww < 8; ++ww) r += red[t * 8 + ww];
                if (tok0 + t < sz.outN) out[tok0 + t] = r;
            }
        }
    }
}

// ---- size-based input resolution (elements OR bytes; any ordering) ----------
extern "C" void kernel_launch(void* const* d_in, const int* in_sizes, int n_in,
                              void* d_out, int out_size) {
    long long es[64];
    int m = n_in > 64 ? 64 : n_in;
    bool bytemode = false;
    for (int i = 0; i < m; ++i) if (in_sizes[i] == 4194304) bytemode = true;
    for (int i = 0; i < m; ++i)
        es[i] = bytemode ? (long long)in_sizes[i] / 4 : (long long)in_sizes[i];
    long long outN = bytemode ? (long long)out_size / 4 : (long long)out_size;

    int iCoord = -1, iLat = -1, iW0 = -1, iB4 = -1;
    int idx65[3];  int n65 = 0;
    int idx256[5]; int n256 = 0;
    for (int i = 0; i < m; ++i) {
        long long s = es[i];
        if      (s == 262144)  iCoord = i;
        else if (s == 1048576) iLat   = i;
        else if (s == 52480)   iW0    = i;
        else if (s == 1)       iB4    = i;
        else if (s == 65536 && n65 < 3)  idx65[n65++]  = i;
        else if (s == 256   && n256 < 5) idx256[n256++] = i;
    }

    int iW1, iW2, iW3, iW4, iB0, iB1, iB2, iB3;
    if (n65 == 3 && n256 == 5 && iCoord >= 0 && iLat >= 0 && iW0 >= 0 && iB4 >= 0) {
        iW1 = idx65[0]; iW2 = idx65[1]; iW3 = idx65[2];
        if (idx256[0] < idx65[0]) {     // biases interleaved (declaration order)
            iB0 = idx256[0]; iB1 = idx256[1]; iB2 = idx256[2];
            iB3 = idx256[3]; iW4 = idx256[4];
        } else {                        // W-block first (sorted order)
            iW4 = idx256[0]; iB0 = idx256[1]; iB1 = idx256[2];
            iB2 = idx256[3]; iB3 = idx256[4];
        }
    } else {
        iCoord = 0 % m;  iLat = 1 % m;  iW0 = 2 % m;  iB0 = 3 % m;
        iW1 = 4 % m;     iB1 = 5 % m;   iW2 = 6 % m;  iB2 = 7 % m;
        iW3 = 8 % m;     iB3 = 9 % m;   iW4 = 10 % m; iB4 = 11 % m;
    }

    Sizes sz;
    sz.c = (int)es[iCoord]; sz.outN = (int)outN;

    const float* coord  = (const float*)d_in[iCoord];
    const float* latent = (const float*)d_in[iLat];
    const float* W0 = (const float*)d_in[iW0]; const float* b0 = (const float*)d_in[iB0];
    const float* W1 = (const float*)d_in[iW1]; const float* b1 = (const float*)d_in[iB1];
    const float* W2 = (const float*)d_in[iW2]; const float* b2 = (const float*)d_in[iB2];
    const float* W3 = (const float*)d_in[iW3]; const float* b3 = (const float*)d_in[iB3];
    const float* W4 = (const float*)d_in[iW4]; const float* b4 = (const float*)d_in[iB4];

    prep_kernel<<<dim3(HH, 4), HH>>>(W0, W1, W2, W3);

    cudaFuncSetAttribute(lisa_mma, cudaFuncAttributeMaxDynamicSharedMemorySize,
                         SMEM_DYN);
    int blocks = (int)((outN + MT - 1) / MT);    // 2048 expected
    lisa_mma<<<blocks, NTHR, SMEM_DYN>>>(coord, latent, b0, b1, b2, b3, W4, b4,
                                         (float*)d_out, sz);
}

// round 14
// speedup vs baseline: 2.2778x; 1.5113x over previous
#include <cuda_runtime.h>
#include <cuda_fp16.h>
#include <cstdint>

#define LLEN 32768
#define NN 2048
#define DD 64
#define HH 256
#define KIN 205
#define MT 128                   // tokens per CTA (M)
#define NTHR 512
#define ASTRB 512                // A row stride bytes (256 fp16, XOR-swizzled)
#define A_BYTES (MT * ASTRB)     // 65536 (single fp16 A)
#define OFF_B   A_BYTES          // 65536
#define BSTAGE 16384             // B stage bytes (256 rows x 64B, K=32, fp16)
#define NSTG 4
#define SMEM_DYN (OFF_B + NSTG * BSTAGE)   // 131072 (1 CTA/SM)

struct Sizes { int c, outN; };

// ---- device scratch: transposed fp16 weights  B[l][n][k] --------------------
__device__ __half g_B16[4][HH * HH];

// ---- helpers ----------------------------------------------------------------
__device__ __forceinline__ uint32_t smem_u32(const void* p) {
    uint32_t a;
    asm("{ .reg .u64 t; cvta.to.shared.u64 t, %1; cvt.u32.u64 %0, t; }"
        : "=r"(a) : "l"(p));
    return a;
}
__device__ __forceinline__ void ldsm4(uint32_t* r, uint32_t a) {
    asm volatile("ldmatrix.sync.aligned.m8n8.x4.shared.b16 {%0,%1,%2,%3}, [%4];"
                 : "=r"(r[0]), "=r"(r[1]), "=r"(r[2]), "=r"(r[3]) : "r"(a));
}
__device__ __forceinline__ void ldsm2(uint32_t* r, uint32_t a) {
    asm volatile("ldmatrix.sync.aligned.m8n8.x2.shared.b16 {%0,%1}, [%2];"
                 : "=r"(r[0]), "=r"(r[1]) : "r"(a));
}
__device__ __forceinline__ void mmah(float* c, const uint32_t* a, const uint32_t* b) {
    asm volatile("mma.sync.aligned.m16n8k16.row.col.f32.f16.f16.f32 "
                 "{%0,%1,%2,%3}, {%4,%5,%6,%7}, {%8,%9}, {%0,%1,%2,%3};"
                 : "+f"(c[0]), "+f"(c[1]), "+f"(c[2]), "+f"(c[3])
                 : "r"(a[0]), "r"(a[1]), "r"(a[2]), "r"(a[3]),
                   "r"(b[0]), "r"(b[1]));
}
__device__ __forceinline__ uint32_t pack_h2(float x, float y) {
    __half hx = __float2half(x), hy = __float2half(y);
    return (uint32_t)__half_as_ushort(hx)
         | ((uint32_t)__half_as_ushort(hy) << 16);
}
__device__ __forceinline__ void cp16(uint32_t dst, const void* src) {
    asm volatile("cp.async.cg.shared.global [%0], [%1], 16;"
                 :: "r"(dst), "l"(src));
}
// swizzled A element byte offset (2B elements, 512B rows, 16B-chunk XOR row&7)
__device__ __forceinline__ uint32_t a_off(int m, int ch) {
    return (uint32_t)(m * ASTRB + (((ch >> 3) ^ (m & 7)) << 4) + ((ch & 7) << 1));
}

// panel p (K rows [32p,32p+32)) of layer weights -> stage st; all 512 threads
__device__ __forceinline__ void issue_panel(uint32_t bBU, int st,
                                            const __half* gw, int p, int t)
{
#pragma unroll
    for (int q4 = 0; q4 < 2; ++q4) {
        int c  = q4 * 512 + t;                 // 0..1023 chunks of 16B
        int n = c >> 2, q = c & 3;             // 4 chunks = 64B per row
        const __half* src = gw + n * HH + p * 32 + q * 8;
        uint32_t dst = bBU + (uint32_t)(st * BSTAGE + n * 64 + ((q ^ (n & 3)) << 4));
        cp16(dst, src);
    }
    asm volatile("cp.async.commit_group;" ::: "memory");
}

// ---- prep: transpose + fp16 round of layer weights --------------------------
__global__ void prep_kernel(const float* __restrict__ W0, const float* __restrict__ W1,
                            const float* __restrict__ W2, const float* __restrict__ W3)
{
    int n = blockIdx.x;              // output channel
    int l = blockIdx.y;              // layer
    int k = threadIdx.x;             // input channel
    const float* W = (l == 0) ? W0 : (l == 1) ? W1 : (l == 2) ? W2 : W3;
    float v = 0.f;
    if (l != 0 || k < KIN) v = __ldg(W + k * HH + n);
    g_B16[l][n * HH + k] = __float2half(v);
}

// ---- main fused kernel ------------------------------------------------------
__global__ void __launch_bounds__(NTHR, 1)
lisa_mma(const float* __restrict__ coord, const float* __restrict__ latent,
         const float* __restrict__ b0, const float* __restrict__ b1,
         const float* __restrict__ b2, const float* __restrict__ b3,
         const float* __restrict__ W4, const float* __restrict__ b4,
         float* __restrict__ out, Sizes sz)
{
    extern __shared__ char sm[];
    const uint32_t sm0 = smem_u32(sm);
    const uint32_t aU = sm0, bBU = sm0 + OFF_B;

    const int t = threadIdx.x, wid = t >> 5, lane = t & 31;
    const int mh = wid >> 3;                 // M-half 0/1 (64 tokens each)
    const int nw = wid & 7;                  // N-slice warp (32 cols)
    const int tok0 = blockIdx.x * MT;
    const int bb = tok0 / LLEN;
    const float* lat = latent + bb * NN * DD;

    // prefetch layer-0 panels 0..2 (overlaps the feature build below)
    issue_panel(bBU, 0, g_B16[0], 0, t);
    issue_panel(bBU, 1, g_B16[0], 1, t);
    issue_panel(bBU, 2, g_B16[0], 2, t);

    // ---- feature build: coord | PE(12) | sampled(192) | zeros, fp16 ---------
#pragma unroll 2
    for (int tt = 0; tt < 8; ++tt) {
        int m = wid * 8 + tt;                // 16 warps x 8 = 128 tokens
        float c = __ldg(coord + min(tok0 + m, sz.c - 1));
        float ix = c * (float)NN - 0.5f;
        float x0f = floorf(ix);
        float fr = ix - x0f, om = 1.f - fr;
        int x0 = (int)x0f;
        int i0 = min(max(x0, 0), NN - 1);
        int i1 = min(max(x0 + 1, 0), NN - 1);
#pragma unroll
        for (int r = 0; r < 8; ++r) {
            int ch = r * 32 + lane;
            float v = 0.f;
            if (ch == 0) v = c;
            else if (ch < 13) {
                int k = ch - 1;
                float ang = c * (float)(1 << (k >> 1));
                v = (k & 1) ? cosf(ang) : sinf(ang);
            } else if (ch < 205) {
                int u = ch - 13, s = u >> 6, d = u & 63;
                int j0 = min(max(i0 + s - 1, 0), NN - 1);
                int j1 = min(max(i1 + s - 1, 0), NN - 1);
                v = om * __ldg(lat + j0 * DD + d) + fr * __ldg(lat + j1 * DD + d);
            }
            *reinterpret_cast<__half*>(sm + a_off(m, ch)) = __float2half(v);
        }
    }

    const float* bgs[4] = { b0, b1, b2, b3 };

#pragma unroll 1
    for (int l = 0; l < 4; ++l) {
        const int nP = (l == 0) ? 7 : 8;     // layer0 K=224 (205 + zero pad)

        float C[4][4][4];
#pragma unroll
        for (int a = 0; a < 4; ++a)
#pragma unroll
            for (int b = 0; b < 4; ++b)
#pragma unroll
                for (int q = 0; q < 4; ++q) C[a][b][q] = 0.f;

#pragma unroll 1
        for (int p = 0; p < nP; ++p) {
            // pending groups: p, p+1, p+2 (those that exist)
            if (p + 1 >= nP) {
                asm volatile("cp.async.wait_group 0;" ::: "memory");
            } else if (p + 2 >= nP) {
                asm volatile("cp.async.wait_group 1;" ::: "memory");
            } else {
                asm volatile("cp.async.wait_group 2;" ::: "memory");
            }
            __syncthreads();     // panel p visible; stage (p+3)%4 free; A ordered

            if (p + 3 < nP)
                issue_panel(bBU, (p + 3) % NSTG, g_B16[l], p + 3, t);

            const uint32_t bU = bBU + (uint32_t)((p % NSTG) * BSTAGE);
#pragma unroll
            for (int ks = 0; ks < 2; ++ks) {
                uint32_t bh[4][2];
#pragma unroll
                for (int nt = 0; nt < 4; ++nt) {
                    int row = nw * 32 + nt * 8 + (lane & 7);
                    int chk = 2 * ks + ((lane >> 3) & 1);
                    uint32_t rowb = bU + (uint32_t)(row * 64 + ((chk ^ (row & 3)) << 4));
                    ldsm2(bh[nt], rowb);
                }
#pragma unroll
                for (int mt = 0; mt < 4; ++mt) {
                    uint32_t ah[4];
                    int row = mh * 64 + mt * 16 + (lane & 15);
                    int chk = p * 4 + ks * 2 + (lane >> 4);
                    uint32_t ra = aU + (uint32_t)(row * ASTRB
                                                  + ((chk ^ (row & 7)) << 4));
                    ldsm4(ah, ra);
#pragma unroll
                    for (int nt = 0; nt < 4; ++nt) mmah(C[mt][nt], ah, bh[nt]);
                }
            }
        }
        __syncthreads();         // all compute done: A writable, B stages free

        if (l < 3) {             // prefetch next layer's first panels over epilogue
            issue_panel(bBU, 0, g_B16[l + 1], 0, t);
            issue_panel(bBU, 1, g_B16[l + 1], 1, t);
            issue_panel(bBU, 2, g_B16[l + 1], 2, t);
        }

        const float* bg = bgs[l];
        if (l < 3) {
            // bias + relu + fp16 round into A (k-layout for next layer)
#pragma unroll
            for (int nt = 0; nt < 4; ++nt) {
                int n0 = nw * 32 + nt * 8 + (lane & 3) * 2;
                float bi0 = __ldg(bg + n0), bi1 = __ldg(bg + n0 + 1);
#pragma unroll
                for (int mt = 0; mt < 4; ++mt) {
                    int m0 = mh * 64 + mt * 16 + (lane >> 2);
                    float v0 = fmaxf(C[mt][nt][0] + bi0, 0.f);
                    float v1 = fmaxf(C[mt][nt][1] + bi1, 0.f);
                    float v2 = fmaxf(C[mt][nt][2] + bi0, 0.f);
                    float v3 = fmaxf(C[mt][nt][3] + bi1, 0.f);
                    *reinterpret_cast<uint32_t*>(sm + a_off(m0, n0))     = pack_h2(v0, v1);
                    *reinterpret_cast<uint32_t*>(sm + a_off(m0 + 8, n0)) = pack_h2(v2, v3);
                }
            }
            // next layer's iter-0 sync orders these writes before ldmatrix
        } else {
            // final: bias+relu, dot with W4, reduce 256->1 per token
            float slo[4] = {0.f, 0.f, 0.f, 0.f}, shi[4] = {0.f, 0.f, 0.f, 0.f};
#pragma unroll
            for (int nt = 0; nt < 4; ++nt) {
                int n0 = nw * 32 + nt * 8 + (lane & 3) * 2;
                float bi0 = __ldg(bg + n0), bi1 = __ldg(bg + n0 + 1);
                float w0 = __ldg(W4 + n0), w1 = __ldg(W4 + n0 + 1);
#pragma unroll
                for (int mt = 0; mt < 4; ++mt) {
                    slo[mt] += fmaxf(C[mt][nt][0] + bi0, 0.f) * w0
                             + fmaxf(C[mt][nt][1] + bi1, 0.f) * w1;
                    shi[mt] += fmaxf(C[mt][nt][2] + bi0, 0.f) * w0
                             + fmaxf(C[mt][nt][3] + bi1, 0.f) * w1;
                }
            }
#pragma unroll
            for (int mt = 0; mt < 4; ++mt) {
                slo[mt] += __shfl_xor_sync(0xffffffffu, slo[mt], 1);
                slo[mt] += __shfl_xor_sync(0xffffffffu, slo[mt], 2);
                shi[mt] += __shfl_xor_sync(0xffffffffu, shi[mt], 1);
                shi[mt] += __shfl_xor_sync(0xffffffffu, shi[mt], 2);
            }
            float* red = reinterpret_cast<float*>(sm + OFF_B);   // 128 x 8 floats
            if ((lane & 3) == 0) {
                int g = lane >> 2;
#pragma unroll
                for (int mt = 0; mt < 4; ++mt) {
                    int m0 = mh * 64 + mt * 16 + g;
                    red[m0 * 8 + nw]       = slo[mt];
                    red[(m0 + 8) * 8 + nw] = shi[mt];
                }
            }
            __syncthreads();
            if (t < MT) {
                float r = __ldg(b4);
#pragma unroll
                for (int ww = 0; ww < 8; ++ww) r += red[t * 8 + ww];
                if (tok0 + t < sz.outN) out[tok0 + t] = r;
            }
        }
    }
}

// ---- size-based input resolution (elements OR bytes; any ordering) ----------
extern "C" void kernel_launch(void* const* d_in, const int* in_sizes, int n_in,
                              void* d_out, int out_size) {
    long long es[64];
    int m = n_in > 64 ? 64 : n_in;
    bool bytemode = false;
    for (int i = 0; i < m; ++i) if (in_sizes[i] == 4194304) bytemode = true;
    for (int i = 0; i < m; ++i)
        es[i] = bytemode ? (long long)in_sizes[i] / 4 : (long long)in_sizes[i];
    long long outN = bytemode ? (long long)out_size / 4 : (long long)out_size;

    int iCoord = -1, iLat = -1, iW0 = -1, iB4 = -1;
    int idx65[3];  int n65 = 0;
    int idx256[5]; int n256 = 0;
    for (int i = 0; i < m; ++i) {
        long long s = es[i];
        if      (s == 262144)  iCoord = i;
        else if (s == 1048576) iLat   = i;
        else if (s == 52480)   iW0    = i;
        else if (s == 1)       iB4    = i;
        else if (s == 65536 && n65 < 3)  idx65[n65++]  = i;
        else if (s == 256   && n256 < 5) idx256[n256++] = i;
    }

    int iW1, iW2, iW3, iW4, iB0, iB1, iB2, iB3;
    if (n65 == 3 && n256 == 5 && iCoord >= 0 && iLat >= 0 && iW0 >= 0 && iB4 >= 0) {
        iW1 = idx65[0]; iW2 = idx65[1]; iW3 = idx65[2];
        if (idx256[0] < idx65[0]) {     // biases interleaved (declaration order)
            iB0 = idx256[0]; iB1 = idx256[1]; iB2 = idx256[2];
            iB3 = idx256[3]; iW4 = idx256[4];
        } else {                        // W-block first (sorted order)
            iW4 = idx256[0]; iB0 = idx256[1]; iB1 = idx256[2];
            iB2 = idx256[3]; iB3 = idx256[4];
        }
    } else {
        iCoord = 0 % m;  iLat = 1 % m;  iW0 = 2 % m;  iB0 = 3 % m;
        iW1 = 4 % m;     iB1 = 5 % m;   iW2 = 6 % m;  iB2 = 7 % m;
        iW3 = 8 % m;     iB3 = 9 % m;   iW4 = 10 % m; iB4 = 11 % m;
    }

    Sizes sz;
    sz.c = (int)es[iCoord]; sz.outN = (int)outN;

    const float* coord  = (const float*)d_in[iCoord];
    const float* latent = (const float*)d_in[iLat];
    const float* W0 = (const float*)d_in[iW0]; const float* b0 = (const float*)d_in[iB0];
    const float* W1 = (const float*)d_in[iW1]; const float* b1 = (const float*)d_in[iB1];
    const float* W2 = (const float*)d_in[iW2]; const float* b2 = (const float*)d_in[iB2];
    const float* W3 = (const float*)d_in[iW3]; const float* b3 = (const float*)d_in[iB3];
    const float* W4 = (const float*)d_in[iW4]; const float* b4 = (const float*)d_in[iB4];

    prep_kernel<<<dim3(HH, 4), HH>>>(W0, W1, W2, W3);

    cudaFuncSetAttribute(lisa_mma, cudaFuncAttributeMaxDynamicSharedMemorySize,
                         SMEM_DYN);
    int blocks = (int)((outN + MT - 1) / MT);    // 2048 expected
    lisa_mma<<<blocks, NTHR, SMEM_DYN>>>(coord, latent, b0, b1, b2, b3, W4, b4,
                                         (float*)d_out, sz);
}

// round 15
// speedup vs baseline: 2.5876x; 1.1360x over previous
#include <cuda_runtime.h>
#include <cuda_fp16.h>
#include <cstdint>

#define LLEN 32768
#define NN 2048
#define DD 64
#define HH 256
#define KIN 205
#define MT 64                    // tokens per CTA (M)
#define NTHR 256
#define ASTRB 512                // A row stride bytes (256 fp16, XOR-swizzled)
#define A_BYTES (MT * ASTRB)     // 32768
#define OFF_B   A_BYTES
#define BSTAGE 16384             // B stage bytes (256 rows x 64B, K=32, fp16)
#define NSTG 4
#define SMEM_DYN (OFF_B + NSTG * BSTAGE)   // 98304 -> 2 CTAs/SM

struct Sizes { int c, outN; };

// ---- device scratch: transposed fp16 weights  B[l][n][k'] -------------------
// layer-0 channel remap: k' = k (k<13), k' = k+3 (13<=k<205); zeros elsewhere
__device__ __half g_B16[4][HH * HH];

// ---- helpers ----------------------------------------------------------------
__device__ __forceinline__ uint32_t smem_u32(const void* p) {
    uint32_t a;
    asm("{ .reg .u64 t; cvta.to.shared.u64 t, %1; cvt.u32.u64 %0, t; }"
        : "=r"(a) : "l"(p));
    return a;
}
__device__ __forceinline__ void ldsm4(uint32_t* r, uint32_t a) {
    asm volatile("ldmatrix.sync.aligned.m8n8.x4.shared.b16 {%0,%1,%2,%3}, [%4];"
                 : "=r"(r[0]), "=r"(r[1]), "=r"(r[2]), "=r"(r[3]) : "r"(a));
}
__device__ __forceinline__ void ldsm2(uint32_t* r, uint32_t a) {
    asm volatile("ldmatrix.sync.aligned.m8n8.x2.shared.b16 {%0,%1}, [%2];"
                 : "=r"(r[0]), "=r"(r[1]) : "r"(a));
}
__device__ __forceinline__ void mmah(float* c, const uint32_t* a, const uint32_t* b) {
    asm volatile("mma.sync.aligned.m16n8k16.row.col.f32.f16.f16.f32 "
                 "{%0,%1,%2,%3}, {%4,%5,%6,%7}, {%8,%9}, {%0,%1,%2,%3};"
                 : "+f"(c[0]), "+f"(c[1]), "+f"(c[2]), "+f"(c[3])
                 : "r"(a[0]), "r"(a[1]), "r"(a[2]), "r"(a[3]),
                   "r"(b[0]), "r"(b[1]));
}
__device__ __forceinline__ uint32_t pack_h2(float x, float y) {
    __half hx = __float2half(x), hy = __float2half(y);
    return (uint32_t)__half_as_ushort(hx)
         | ((uint32_t)__half_as_ushort(hy) << 16);
}
__device__ __forceinline__ void cp16(uint32_t dst, const void* src) {
    asm volatile("cp.async.cg.shared.global [%0], [%1], 16;"
                 :: "r"(dst), "l"(src));
}
// swizzled A element byte offset (2B elements, 512B rows, 16B-chunk XOR row&7)
__device__ __forceinline__ uint32_t a_off(int m, int ch) {
    return (uint32_t)(m * ASTRB + (((ch >> 3) ^ (m & 7)) << 4) + ((ch & 7) << 1));
}

// panel p (K rows [32p,32p+32)) of layer weights -> stage st; 256 threads
__device__ __forceinline__ void issue_panel(uint32_t bBU, int st,
                                            const __half* gw, int p, int t)
{
#pragma unroll
    for (int q4 = 0; q4 < 4; ++q4) {
        int c  = q4 * 256 + t;                 // 0..1023 chunks of 16B
        int n = c >> 2, q = c & 3;             // 4 chunks = 64B per row
        const __half* src = gw + n * HH + p * 32 + q * 8;
        uint32_t dst = bBU + (uint32_t)(st * BSTAGE + n * 64 + ((q ^ (n & 3)) << 4));
        cp16(dst, src);
    }
    asm volatile("cp.async.commit_group;" ::: "memory");
}

// ---- prep: transpose + fp16 round + layer-0 channel remap -------------------
__global__ void prep_kernel(const float* __restrict__ W0, const float* __restrict__ W1,
                            const float* __restrict__ W2, const float* __restrict__ W3)
{
    int n = blockIdx.x;              // output channel
    int l = blockIdx.y;              // layer
    int k = threadIdx.x;             // NEW input channel k'
    float v = 0.f;
    if (l == 0) {
        int ks = (k < 13) ? k : ((k >= 16 && k < 208) ? k - 3 : -1);
        if (ks >= 0) v = __ldg(W0 + ks * HH + n);
    } else {
        const float* W = (l == 1) ? W1 : (l == 2) ? W2 : W3;
        v = __ldg(W + k * HH + n);
    }
    g_B16[l][n * HH + k] = __float2half(v);
}

// ---- main fused kernel ------------------------------------------------------
__global__ void __launch_bounds__(NTHR, 2)
lisa_mma(const float* __restrict__ coord, const float* __restrict__ latent,
         const float* __restrict__ b0, const float* __restrict__ b1,
         const float* __restrict__ b2, const float* __restrict__ b3,
         const float* __restrict__ W4, const float* __restrict__ b4,
         float* __restrict__ out, Sizes sz)
{
    extern __shared__ char sm[];
    const uint32_t sm0 = smem_u32(sm);
    const uint32_t aU = sm0, bBU = sm0 + OFF_B;

    const int t = threadIdx.x, wid = t >> 5, lane = t & 31;
    const int nw = wid;                      // N-slice warp (32 cols each)
    const int tok0 = blockIdx.x * MT;
    const int bb = tok0 / LLEN;
    const float* lat = latent + bb * NN * DD;

    // prefetch layer-0 panels 0..2 (overlaps the feature build below)
    issue_panel(bBU, 0, g_B16[0], 0, t);
    issue_panel(bBU, 1, g_B16[0], 1, t);
    issue_panel(bBU, 2, g_B16[0], 2, t);

    // ---- feature build (channel-remapped layout) ----------------------------
    // ch 0..12: coord|PE, 13..15: 0, 16..207: sampled (s*64+d), 208..223: 0
#pragma unroll 2
    for (int tt = 0; tt < 8; ++tt) {
        int m = wid * 8 + tt;                // 8 warps x 8 = 64 tokens
        float c = __ldg(coord + min(tok0 + m, sz.c - 1));
        float ix = c * (float)NN - 0.5f;
        float x0f = floorf(ix);
        float fr = ix - x0f, om = 1.f - fr;
        int x0 = (int)x0f;
        int i0 = min(max(x0, 0), NN - 1);
        int i1 = min(max(x0 + 1, 0), NN - 1);
        int off = (i1 > i0) ? 1 : 0;         // border-clamp exactness
        float2 rv[4];
#pragma unroll
        for (int j = 0; j < 4; ++j) {
            int rr = min(max(i0 - 1 + j, 0), NN - 1);
            rv[j] = __ldg(reinterpret_cast<const float2*>(lat + rr * DD + 2 * lane));
        }
#pragma unroll
        for (int s = 0; s < 3; ++s) {
            float2 f0 = rv[s], f1 = rv[s + off];
            float v0 = om * f0.x + fr * f1.x;
            float v1 = om * f0.y + fr * f1.y;
            *reinterpret_cast<uint32_t*>(sm + a_off(m, 16 + s * 64 + 2 * lane))
                = pack_h2(v0, v1);
        }
        float v = 0.f;
        if (lane == 0) v = c;
        else if (lane < 13) {
            int k = lane - 1;
            float ang = c * (float)(1 << (k >> 1));
            v = (k & 1) ? cosf(ang) : sinf(ang);
        }
        int chz = (lane < 16) ? lane : (192 + lane);     // 0..15 | 208..223
        *reinterpret_cast<__half*>(sm + a_off(m, chz)) = __float2half(v);
    }

    const float* bgs[4] = { b0, b1, b2, b3 };

#pragma unroll 1
    for (int l = 0; l < 4; ++l) {
        const int nP = (l == 0) ? 7 : 8;     // layer0 K=224

        float C[4][4][4];
#pragma unroll
        for (int a = 0; a < 4; ++a)
#pragma unroll
            for (int b = 0; b < 4; ++b)
#pragma unroll
                for (int q = 0; q < 4; ++q) C[a][b][q] = 0.f;

#pragma unroll 1
        for (int p = 0; p < nP; ++p) {
            if (p + 1 >= nP) {
                asm volatile("cp.async.wait_group 0;" ::: "memory");
            } else if (p + 2 >= nP) {
                asm volatile("cp.async.wait_group 1;" ::: "memory");
            } else {
                asm volatile("cp.async.wait_group 2;" ::: "memory");
            }
            __syncthreads();     // panel p visible; stage (p+3)%4 free; A ordered

            if (p + 3 < nP)
                issue_panel(bBU, (p + 3) % NSTG, g_B16[l], p + 3, t);

            const uint32_t bU = bBU + (uint32_t)((p % NSTG) * BSTAGE);
#pragma unroll
            for (int ks = 0; ks < 2; ++ks) {
                uint32_t bh[4][2];
#pragma unroll
                for (int nt = 0; nt < 4; ++nt) {
                    int row = nw * 32 + nt * 8 + (lane & 7);
                    int chk = 2 * ks + ((lane >> 3) & 1);
                    uint32_t rowb = bU + (uint32_t)(row * 64 + ((chk ^ (row & 3)) << 4));
                    ldsm2(bh[nt], rowb);
                }
#pragma unroll
                for (int mt = 0; mt < 4; ++mt) {
                    uint32_t ah[4];
                    int row = mt * 16 + (lane & 15);
                    int chk = p * 4 + ks * 2 + (lane >> 4);
                    uint32_t ra = aU + (uint32_t)(row * ASTRB
                                                  + ((chk ^ (row & 7)) << 4));
                    ldsm4(ah, ra);
#pragma unroll
                    for (int nt = 0; nt < 4; ++nt) mmah(C[mt][nt], ah, bh[nt]);
                }
            }
        }
        __syncthreads();         // all compute done: A writable, B stages free

        if (l < 3) {             // prefetch next layer's first panels over epilogue
            issue_panel(bBU, 0, g_B16[l + 1], 0, t);
            issue_panel(bBU, 1, g_B16[l + 1], 1, t);
            issue_panel(bBU, 2, g_B16[l + 1], 2, t);
        }

        const float* bg = bgs[l];
        if (l < 3) {
            // bias + relu + fp16 round into A (k-layout for next layer)
#pragma unroll
            for (int nt = 0; nt < 4; ++nt) {
                int n0 = nw * 32 + nt * 8 + (lane & 3) * 2;
                float bi0 = __ldg(bg + n0), bi1 = __ldg(bg + n0 + 1);
#pragma unroll
                for (int mt = 0; mt < 4; ++mt) {
                    int m0 = mt * 16 + (lane >> 2);
                    float v0 = fmaxf(C[mt][nt][0] + bi0, 0.f);
                    float v1 = fmaxf(C[mt][nt][1] + bi1, 0.f);
                    float v2 = fmaxf(C[mt][nt][2] + bi0, 0.f);
                    float v3 = fmaxf(C[mt][nt][3] + bi1, 0.f);
                    *reinterpret_cast<uint32_t*>(sm + a_off(m0, n0))     = pack_h2(v0, v1);
                    *reinterpret_cast<uint32_t*>(sm + a_off(m0 + 8, n0)) = pack_h2(v2, v3);
                }
            }
            // next layer's iter-0 sync orders these writes before ldmatrix
        } else {
            // final: bias+relu, dot with W4, reduce 256->1 per token
            float slo[4] = {0.f, 0.f, 0.f, 0.f}, shi[4] = {0.f, 0.f, 0.f, 0.f};
#pragma unroll
            for (int nt = 0; nt < 4; ++nt) {
                int n0 = nw * 32 + nt * 8 + (lane & 3) * 2;
                float bi0 = __ldg(bg + n0), bi1 = __ldg(bg + n0 + 1);
                float w0 = __ldg(W4 + n0), w1 = __ldg(W4 + n0 + 1);
#pragma unroll
                for (int mt = 0; mt < 4; ++mt) {
                    slo[mt] += fmaxf(C[mt][nt][0] + bi0, 0.f) * w0
                             + fmaxf(C[mt][nt][1] + bi1, 0.f) * w1;
                    shi[mt] += fmaxf(C[mt][nt][2] + bi0, 0.f) * w0
                             + fmaxf(C[mt][nt][3] + bi1, 0.f) * w1;
                }
            }
#pragma unroll
            for (int mt = 0; mt < 4; ++mt) {
                slo[mt] += __shfl_xor_sync(0xffffffffu, slo[mt], 1);
                slo[mt] += __shfl_xor_sync(0xffffffffu, slo[mt], 2);
                shi[mt] += __shfl_xor_sync(0xffffffffu, shi[mt], 1);
                shi[mt] += __shfl_xor_sync(0xffffffffu, shi[mt], 2);
            }
            float* red = reinterpret_cast<float*>(sm + OFF_B);   // 64 x 8 floats
            if ((lane & 3) == 0) {
                int g = lane >> 2;
#pragma unroll
                for (int mt = 0; mt < 4; ++mt) {
                    int m0 = mt * 16 + g;
                    red[m0 * 8 + nw]       = slo[mt];
                    red[(m0 + 8) * 8 + nw] = shi[mt];
                }
            }
            __syncthreads();
            if (t < MT) {
                float r = __ldg(b4);
#pragma unroll
                for (int ww = 0; ww < 8; ++ww) r += red[t * 8 + ww];
                if (tok0 + t < sz.outN) out[tok0 + t] = r;
            }
        }
    }
}

// ---- size-based input resolution (elements OR bytes; any ordering) ----------
extern "C" void kernel_launch(void* const* d_in, const int* in_sizes, int n_in,
                              void* d_out, int out_size) {
    long long es[64];
    int m = n_in > 64 ? 64 : n_in;
    bool bytemode = false;
    for (int i = 0; i < m; ++i) if (in_sizes[i] == 4194304) bytemode = true;
    for (int i = 0; i < m; ++i)
        es[i] = bytemode ? (long long)in_sizes[i] / 4 : (long long)in_sizes[i];
    long long outN = bytemode ? (long long)out_size / 4 : (long long)out_size;

    int iCoord = -1, iLat = -1, iW0 = -1, iB4 = -1;
    int idx65[3];  int n65 = 0;
    int idx256[5]; int n256 = 0;
    for (int i = 0; i < m; ++i) {
        long long s = es[i];
        if      (s == 262144)  iCoord = i;
        else if (s == 1048576) iLat   = i;
        else if (s == 52480)   iW0    = i;
        else if (s == 1)       iB4    = i;
        else if (s == 65536 && n65 < 3)  idx65[n65++]  = i;
        else if (s == 256   && n256 < 5) idx256[n256++] = i;
    }

    int iW1, iW2, iW3, iW4, iB0, iB1, iB2, iB3;
    if (n65 == 3 && n256 == 5 && iCoord >= 0 && iLat >= 0 && iW0 >= 0 && iB4 >= 0) {
        iW1 = idx65[0]; iW2 = idx65[1]; iW3 = idx65[2];
        if (idx256[0] < idx65[0]) {     // biases interleaved (declaration order)
            iB0 = idx256[0]; iB1 = idx256[1]; iB2 = idx256[2];
            iB3 = idx256[3]; iW4 = idx256[4];
        } else {                        // W-block first (sorted order)
            iW4 = idx256[0]; iB0 = idx256[1]; iB1 = idx256[2];
            iB2 = idx256[3]; iB3 = idx256[4];
        }
    } else {
        iCoord = 0 % m;  iLat = 1 % m;  iW0 = 2 % m;  iB0 = 3 % m;
        iW1 = 4 % m;     iB1 = 5 % m;   iW2 = 6 % m;  iB2 = 7 % m;
        iW3 = 8 % m;     iB3 = 9 % m;   iW4 = 10 % m; iB4 = 11 % m;
    }

    Sizes sz;
    sz.c = (int)es[iCoord]; sz.outN = (int)outN;

    const float* coord  = (const float*)d_in[iCoord];
    const float* latent = (const float*)d_in[iLat];
    const float* W0 = (const float*)d_in[iW0]; const float* b0 = (const float*)d_in[iB0];
    const float* W1 = (const float*)d_in[iW1]; const float* b1 = (const float*)d_in[iB1];
    const float* W2 = (const float*)d_in[iW2]; const float* b2 = (const float*)d_in[iB2];
    const float* W3 = (const float*)d_in[iW3]; const float* b3 = (const float*)d_in[iB3];
    const float* W4 = (const float*)d_in[iW4]; const float* b4 = (const float*)d_in[iB4];

    prep_kernel<<<dim3(HH, 4), HH>>>(W0, W1, W2, W3);

    cudaFuncSetAttribute(lisa_mma, cudaFuncAttributeMaxDynamicSharedMemorySize,
                         SMEM_DYN);
    int blocks = (int)((outN + MT - 1) / MT);    // 4096 expected
    lisa_mma<<<blocks, NTHR, SMEM_DYN>>>(coord, latent, b0, b1, b2, b3, W4, b4,
                                         (float*)d_out, sz);
}

// round 16
// speedup vs baseline: 2.7157x; 1.0495x over previous
#include <cuda_runtime.h>
#include <cuda_fp16.h>
#include <cstdint>

#define LLEN 32768
#define NN 2048
#define DD 64
#define HH 256
#define KIN 205
#define MT 64                    // tokens per CTA (M)
#define NTHR 256
#define ASTRB 512                // A row stride bytes (256 fp16, XOR-swizzled)
#define A_BYTES (MT * ASTRB)     // 32768
#define OFF_B   A_BYTES
#define BSTAGE 16384             // B stage bytes (256 rows x 64B, K=32, fp16)
#define NSTG 5
#define SMEM_DYN (OFF_B + NSTG * BSTAGE)   // 114688 -> 2 CTAs/SM (229376<=233472)

struct Sizes { int c, outN; };

// ---- device scratch: transposed fp16 weights  B[l][n][k'] -------------------
// layer-0 channel remap: k' = k (k<13), k' = k+3 (13<=k<205); zeros elsewhere
__device__ __half g_B16[4][HH * HH];

// ---- helpers ----------------------------------------------------------------
__device__ __forceinline__ uint32_t smem_u32(const void* p) {
    uint32_t a;
    asm("{ .reg .u64 t; cvta.to.shared.u64 t, %1; cvt.u32.u64 %0, t; }"
        : "=r"(a) : "l"(p));
    return a;
}
__device__ __forceinline__ void ldsm4(uint32_t* r, uint32_t a) {
    asm volatile("ldmatrix.sync.aligned.m8n8.x4.shared.b16 {%0,%1,%2,%3}, [%4];"
                 : "=r"(r[0]), "=r"(r[1]), "=r"(r[2]), "=r"(r[3]) : "r"(a));
}
__device__ __forceinline__ void ldsm2(uint32_t* r, uint32_t a) {
    asm volatile("ldmatrix.sync.aligned.m8n8.x2.shared.b16 {%0,%1}, [%2];"
                 : "=r"(r[0]), "=r"(r[1]) : "r"(a));
}
__device__ __forceinline__ void mmah(float* c, const uint32_t* a, const uint32_t* b) {
    asm volatile("mma.sync.aligned.m16n8k16.row.col.f32.f16.f16.f32 "
                 "{%0,%1,%2,%3}, {%4,%5,%6,%7}, {%8,%9}, {%0,%1,%2,%3};"
                 : "+f"(c[0]), "+f"(c[1]), "+f"(c[2]), "+f"(c[3])
                 : "r"(a[0]), "r"(a[1]), "r"(a[2]), "r"(a[3]),
                   "r"(b[0]), "r"(b[1]));
}
// single-instruction fp16x2 pack: x -> low half, y -> high half
__device__ __forceinline__ uint32_t pack_h2(float x, float y) {
    uint32_t r;
    asm("cvt.rn.f16x2.f32 %0, %1, %2;" : "=r"(r) : "f"(y), "f"(x));
    return r;
}
__device__ __forceinline__ void cp16(uint32_t dst, const void* src) {
    asm volatile("cp.async.cg.shared.global [%0], [%1], 16;"
                 :: "r"(dst), "l"(src));
}
// swizzled A element byte offset (2B elements, 512B rows, 16B-chunk XOR row&7)
__device__ __forceinline__ uint32_t a_off(int m, int ch) {
    return (uint32_t)(m * ASTRB + (((ch >> 3) ^ (m & 7)) << 4) + ((ch & 7) << 1));
}

// panel p (K rows [32p,32p+32)) of layer weights -> stage st; 256 threads
__device__ __forceinline__ void issue_panel(uint32_t bBU, int st,
                                            const __half* gw, int p, int t)
{
#pragma unroll
    for (int q4 = 0; q4 < 4; ++q4) {
        int c  = q4 * 256 + t;                 // 0..1023 chunks of 16B
        int n = c >> 2, q = c & 3;             // 4 chunks = 64B per row
        const __half* src = gw + n * HH + p * 32 + q * 8;
        uint32_t dst = bBU + (uint32_t)(st * BSTAGE + n * 64 + ((q ^ (n & 3)) << 4));
        cp16(dst, src);
    }
    asm volatile("cp.async.commit_group;" ::: "memory");
}

// ---- prep: transpose + fp16 round + layer-0 channel remap -------------------
__global__ void prep_kernel(const float* __restrict__ W0, const float* __restrict__ W1,
                            const float* __restrict__ W2, const float* __restrict__ W3)
{
    int n = blockIdx.x;              // output channel
    int l = blockIdx.y;              // layer
    int k = threadIdx.x;             // NEW input channel k'
    float v = 0.f;
    if (l == 0) {
        int ks = (k < 13) ? k : ((k >= 16 && k < 208) ? k - 3 : -1);
        if (ks >= 0) v = __ldg(W0 + ks * HH + n);
    } else {
        const float* W = (l == 1) ? W1 : (l == 2) ? W2 : W3;
        v = __ldg(W + k * HH + n);
    }
    g_B16[l][n * HH + k] = __float2half(v);
}

// ---- main fused kernel ------------------------------------------------------
__global__ void __launch_bounds__(NTHR, 2)
lisa_mma(const float* __restrict__ coord, const float* __restrict__ latent,
         const float* __restrict__ b0, const float* __restrict__ b1,
         const float* __restrict__ b2, const float* __restrict__ b3,
         const float* __restrict__ W4, const float* __restrict__ b4,
         float* __restrict__ out, Sizes sz)
{
    extern __shared__ char sm[];
    const uint32_t sm0 = smem_u32(sm);
    const uint32_t aU = sm0, bBU = sm0 + OFF_B;

    const int t = threadIdx.x, wid = t >> 5, lane = t & 31;
    const int nw = wid;                      // N-slice warp (32 cols each)
    const int tok0 = blockIdx.x * MT;
    const int bb = tok0 / LLEN;
    const float* lat = latent + bb * NN * DD;

    // prefetch layer-0 panels 0..3 (overlaps the feature build below)
    issue_panel(bBU, 0, g_B16[0], 0, t);
    issue_panel(bBU, 1, g_B16[0], 1, t);
    issue_panel(bBU, 2, g_B16[0], 2, t);
    issue_panel(bBU, 3, g_B16[0], 3, t);

    // ---- feature build (channel-remapped layout) ----------------------------
    // ch 0..12: coord|PE, 13..15: 0, 16..207: sampled (s*64+d), 208..223: 0
#pragma unroll 4
    for (int tt = 0; tt < 8; ++tt) {
        int m = wid * 8 + tt;                // 8 warps x 8 = 64 tokens
        float c = __ldg(coord + min(tok0 + m, sz.c - 1));
        float ix = c * (float)NN - 0.5f;
        float x0f = floorf(ix);
        float fr = ix - x0f, om = 1.f - fr;
        int x0 = (int)x0f;
        int i0 = min(max(x0, 0), NN - 1);
        int i1 = min(max(x0 + 1, 0), NN - 1);
        int off = (i1 > i0) ? 1 : 0;         // border-clamp exactness
        float2 rv[4];
#pragma unroll
        for (int j = 0; j < 4; ++j) {
            int rr = min(max(i0 - 1 + j, 0), NN - 1);
            rv[j] = __ldg(reinterpret_cast<const float2*>(lat + rr * DD + 2 * lane));
        }
#pragma unroll
        for (int s = 0; s < 3; ++s) {
            float2 f0 = rv[s], f1 = rv[s + off];
            float v0 = om * f0.x + fr * f1.x;
            float v1 = om * f0.y + fr * f1.y;
            *reinterpret_cast<uint32_t*>(sm + a_off(m, 16 + s * 64 + 2 * lane))
                = pack_h2(v0, v1);
        }
        float v = 0.f;
        if (lane == 0) v = c;
        else if (lane < 13) {
            int k = lane - 1;
            float ang = c * (float)(1 << (k >> 1));
            v = (k & 1) ? __cosf(ang) : __sinf(ang);
        }
        int chz = (lane < 16) ? lane : (192 + lane);     // 0..15 | 208..223
        *reinterpret_cast<__half*>(sm + a_off(m, chz)) = __float2half(v);
    }

    const float* bgs[4] = { b0, b1, b2, b3 };

#pragma unroll 1
    for (int l = 0; l < 4; ++l) {
        const int nP = (l == 0) ? 7 : 8;     // layer0 K=224

        float C[4][4][4];
#pragma unroll
        for (int a = 0; a < 4; ++a)
#pragma unroll
            for (int b = 0; b < 4; ++b)
#pragma unroll
                for (int q = 0; q < 4; ++q) C[a][b][q] = 0.f;

#pragma unroll 1
        for (int p = 0; p < nP; ++p) {
            // allowed pending groups = min(3, nP-1-p)
            if (p + 1 >= nP) {
                asm volatile("cp.async.wait_group 0;" ::: "memory");
            } else if (p + 2 >= nP) {
                asm volatile("cp.async.wait_group 1;" ::: "memory");
            } else if (p + 3 >= nP) {
                asm volatile("cp.async.wait_group 2;" ::: "memory");
            } else {
                asm volatile("cp.async.wait_group 3;" ::: "memory");
            }
            __syncthreads();     // panel p visible; stage (p+4)%5 free; A ordered

            if (p + 4 < nP)
                issue_panel(bBU, (p + 4) % NSTG, g_B16[l], p + 4, t);

            const uint32_t bU = bBU + (uint32_t)((p % NSTG) * BSTAGE);
#pragma unroll
            for (int ks = 0; ks < 2; ++ks) {
                uint32_t bh[4][2];
#pragma unroll
                for (int nt = 0; nt < 4; ++nt) {
                    int row = nw * 32 + nt * 8 + (lane & 7);
                    int chk = 2 * ks + ((lane >> 3) & 1);
                    uint32_t rowb = bU + (uint32_t)(row * 64 + ((chk ^ (row & 3)) << 4));
                    ldsm2(bh[nt], rowb);
                }
#pragma unroll
                for (int mt = 0; mt < 4; ++mt) {
                    uint32_t ah[4];
                    int row = mt * 16 + (lane & 15);
                    int chk = p * 4 + ks * 2 + (lane >> 4);
                    uint32_t ra = aU + (uint32_t)(row * ASTRB
                                                  + ((chk ^ (row & 7)) << 4));
                    ldsm4(ah, ra);
#pragma unroll
                    for (int nt = 0; nt < 4; ++nt) mmah(C[mt][nt], ah, bh[nt]);
                }
            }
        }
        __syncthreads();         // all compute done: A writable, B stages free

        if (l < 3) {             // prefetch next layer's first panels over epilogue
            issue_panel(bBU, 0, g_B16[l + 1], 0, t);
            issue_panel(bBU, 1, g_B16[l + 1], 1, t);
            issue_panel(bBU, 2, g_B16[l + 1], 2, t);
            issue_panel(bBU, 3, g_B16[l + 1], 3, t);
        }

        const float* bg = bgs[l];
        if (l < 3) {
            // bias + relu + fp16 round into A (k-layout for next layer)
#pragma unroll
            for (int nt = 0; nt < 4; ++nt) {
                int n0 = nw * 32 + nt * 8 + (lane & 3) * 2;
                float bi0 = __ldg(bg + n0), bi1 = __ldg(bg + n0 + 1);
#pragma unroll
                for (int mt = 0; mt < 4; ++mt) {
                    int m0 = mt * 16 + (lane >> 2);
                    float v0 = fmaxf(C[mt][nt][0] + bi0, 0.f);
                    float v1 = fmaxf(C[mt][nt][1] + bi1, 0.f);
                    float v2 = fmaxf(C[mt][nt][2] + bi0, 0.f);
                    float v3 = fmaxf(C[mt][nt][3] + bi1, 0.f);
                    *reinterpret_cast<uint32_t*>(sm + a_off(m0, n0))     = pack_h2(v0, v1);
                    *reinterpret_cast<uint32_t*>(sm + a_off(m0 + 8, n0)) = pack_h2(v2, v3);
                }
            }
            // next layer's iter-0 sync orders these writes before ldmatrix
        } else {
            // final: bias+relu, dot with W4, reduce 256->1 per token
            float slo[4] = {0.f, 0.f, 0.f, 0.f}, shi[4] = {0.f, 0.f, 0.f, 0.f};
#pragma unroll
            for (int nt = 0; nt < 4; ++nt) {
                int n0 = nw * 32 + nt * 8 + (lane & 3) * 2;
                float bi0 = __ldg(bg + n0), bi1 = __ldg(bg + n0 + 1);
                float w0 = __ldg(W4 + n0), w1 = __ldg(W4 + n0 + 1);
#pragma unroll
                for (int mt = 0; mt < 4; ++mt) {
                    slo[mt] += fmaxf(C[mt][nt][0] + bi0, 0.f) * w0
                             + fmaxf(C[mt][nt][1] + bi1, 0.f) * w1;
                    shi[mt] += fmaxf(C[mt][nt][2] + bi0, 0.f) * w0
                             + fmaxf(C[mt][nt][3] + bi1, 0.f) * w1;
                }
            }
#pragma unroll
            for (int mt = 0; mt < 4; ++mt) {
                slo[mt] += __shfl_xor_sync(0xffffffffu, slo[mt], 1);
                slo[mt] += __shfl_xor_sync(0xffffffffu, slo[mt], 2);
                shi[mt] += __shfl_xor_sync(0xffffffffu, shi[mt], 1);
                shi[mt] += __shfl_xor_sync(0xffffffffu, shi[mt], 2);
            }
            float* red = reinterpret_cast<float*>(sm + OFF_B);   // 64 x 8 floats
            if ((lane & 3) == 0) {
                int g = lane >> 2;
#pragma unroll
                for (int mt = 0; mt < 4; ++mt) {
                    int m0 = mt * 16 + g;
                    red[m0 * 8 + nw]       = slo[mt];
                    red[(m0 + 8) * 8 + nw] = shi[mt];
                }
            }
            __syncthreads();
            if (t < MT) {
                float r = __ldg(b4);
#pragma unroll
                for (int ww = 0; ww < 8; ++ww) r += red[t * 8 + ww];
                if (tok0 + t < sz.outN) out[tok0 + t] = r;
            }
        }
    }
}

// ---- size-based input resolution (elements OR bytes; any ordering) ----------
extern "C" void kernel_launch(void* const* d_in, const int* in_sizes, int n_in,
                              void* d_out, int out_size) {
    long long es[64];
    int m = n_in > 64 ? 64 : n_in;
    bool bytemode = false;
    for (int i = 0; i < m; ++i) if (in_sizes[i] == 4194304) bytemode = true;
    for (int i = 0; i < m; ++i)
        es[i] = bytemode ? (long long)in_sizes[i] / 4 : (long long)in_sizes[i];
    long long outN = bytemode ? (long long)out_size / 4 : (long long)out_size;

    int iCoord = -1, iLat = -1, iW0 = -1, iB4 = -1;
    int idx65[3];  int n65 = 0;
    int idx256[5]; int n256 = 0;
    for (int i = 0; i < m; ++i) {
        long long s = es[i];
        if      (s == 262144)  iCoord = i;
        else if (s == 1048576) iLat   = i;
        else if (s == 52480)   iW0    = i;
        else if (s == 1)       iB4    = i;
        else if (s == 65536 && n65 < 3)  idx65[n65++]  = i;
        else if (s == 256   && n256 < 5) idx256[n256++] = i;
    }

    int iW1, iW2, iW3, iW4, iB0, iB1, iB2, iB3;
    if (n65 == 3 && n256 == 5 && iCoord >= 0 && iLat >= 0 && iW0 >= 0 && iB4 >= 0) {
        iW1 = idx65[0]; iW2 = idx65[1]; iW3 = idx65[2];
        if (idx256[0] < idx65[0]) {     // biases interleaved (declaration order)
            iB0 = idx256[0]; iB1 = idx256[1]; iB2 = idx256[2];
            iB3 = idx256[3]; iW4 = idx256[4];
        } else {                        // W-block first (sorted order)
            iW4 = idx256[0]; iB0 = idx256[1]; iB1 = idx256[2];
            iB2 = idx256[3]; iB3 = idx256[4];
        }
    } else {
        iCoord = 0 % m;  iLat = 1 % m;  iW0 = 2 % m;  iB0 = 3 % m;
        iW1 = 4 % m;     iB1 = 5 % m;   iW2 = 6 % m;  iB2 = 7 % m;
        iW3 = 8 % m;     iB3 = 9 % m;   iW4 = 10 % m; iB4 = 11 % m;
    }

    Sizes sz;
    sz.c = (int)es[iCoord]; sz.outN = (int)outN;

    const float* coord  = (const float*)d_in[iCoord];
    const float* latent = (const float*)d_in[iLat];
    const float* W0 = (const float*)d_in[iW0]; const float* b0 = (const float*)d_in[iB0];
    const float* W1 = (const float*)d_in[iW1]; const float* b1 = (const float*)d_in[iB1];
    const float* W2 = (const float*)d_in[iW2]; const float* b2 = (const float*)d_in[iB2];
    const float* W3 = (const float*)d_in[iW3]; const float* b3 = (const float*)d_in[iB3];
    const float* W4 = (const float*)d_in[iW4]; const float* b4 = (const float*)d_in[iB4];

    prep_kernel<<<dim3(HH, 4), HH>>>(W0, W1, W2, W3);

    cudaFuncSetAttribute(lisa_mma, cudaFuncAttributeMaxDynamicSharedMemorySize,
                         SMEM_DYN);
    int blocks = (int)((outN + MT - 1) / MT);    // 4096 expected
    lisa_mma<<<blocks, NTHR, SMEM_DYN>>>(coord, latent, b0, b1, b2, b3, W4, b4,
                                         (float*)d_out, sz);
}

// round 17
// speedup vs baseline: 2.8834x; 1.0618x over previous
#include <cuda_runtime.h>
#include <cuda_fp16.h>
#include <cstdint>

#define LLEN 32768
#define NN 2048
#define DD 64
#define HH 256
#define KIN 205
#define MT 64                    // tokens per CTA (M)
#define NTHR 256
#define ASTRB 512                // A row stride bytes (256 fp16, XOR-swizzled)
#define A_BYTES (MT * ASTRB)     // 32768
#define OFF_B   A_BYTES
#define BSTAGE 16384             // B stage bytes (256 rows x 64B, K=32, fp16)
#define NSTG 5
#define SMEM_DYN (OFF_B + NSTG * BSTAGE)   // 114688 -> 2 CTAs/SM

struct Sizes { int c, outN; };

// ---- device scratch: transposed fp16 weights  B[l][n][k'] -------------------
// layer-0 channel remap: k' = k (k<13), k' = k+3 (13<=k<205); zeros elsewhere
__device__ __half g_B16[4][HH * HH];

// ---- helpers ----------------------------------------------------------------
__device__ __forceinline__ uint32_t smem_u32(const void* p) {
    uint32_t a;
    asm("{ .reg .u64 t; cvta.to.shared.u64 t, %1; cvt.u32.u64 %0, t; }"
        : "=r"(a) : "l"(p));
    return a;
}
__device__ __forceinline__ void ldsm4(uint32_t* r, uint32_t a) {
    asm volatile("ldmatrix.sync.aligned.m8n8.x4.shared.b16 {%0,%1,%2,%3}, [%4];"
                 : "=r"(r[0]), "=r"(r[1]), "=r"(r[2]), "=r"(r[3]) : "r"(a));
}
__device__ __forceinline__ void ldsm2(uint32_t* r, uint32_t a) {
    asm volatile("ldmatrix.sync.aligned.m8n8.x2.shared.b16 {%0,%1}, [%2];"
                 : "=r"(r[0]), "=r"(r[1]) : "r"(a));
}
__device__ __forceinline__ void mmah(float* c, const uint32_t* a, const uint32_t* b) {
    asm volatile("mma.sync.aligned.m16n8k16.row.col.f32.f16.f16.f32 "
                 "{%0,%1,%2,%3}, {%4,%5,%6,%7}, {%8,%9}, {%0,%1,%2,%3};"
                 : "+f"(c[0]), "+f"(c[1]), "+f"(c[2]), "+f"(c[3])
                 : "r"(a[0]), "r"(a[1]), "r"(a[2]), "r"(a[3]),
                   "r"(b[0]), "r"(b[1]));
}
// single-instruction fp16x2 pack: x -> low half, y -> high half
__device__ __forceinline__ uint32_t pack_h2(float x, float y) {
    uint32_t r;
    asm("cvt.rn.f16x2.f32 %0, %1, %2;" : "=r"(r) : "f"(y), "f"(x));
    return r;
}
__device__ __forceinline__ void cp16(uint32_t dst, const void* src) {
    asm volatile("cp.async.cg.shared.global [%0], [%1], 16;"
                 :: "r"(dst), "l"(src));
}
// swizzled A element byte offset (2B elements, 512B rows, 16B-chunk XOR row&7)
__device__ __forceinline__ uint32_t a_off(int m, int ch) {
    return (uint32_t)(m * ASTRB + (((ch >> 3) ^ (m & 7)) << 4) + ((ch & 7) << 1));
}

// panel p (K rows [32p,32p+32)) of layer weights -> stage st; 256 threads
__device__ __forceinline__ void issue_panel(uint32_t bBU, int st,
                                            const __half* gw, int p, int t)
{
#pragma unroll
    for (int q4 = 0; q4 < 4; ++q4) {
        int c  = q4 * 256 + t;                 // 0..1023 chunks of 16B
        int n = c >> 2, q = c & 3;             // 4 chunks = 64B per row
        const __half* src = gw + n * HH + p * 32 + q * 8;
        uint32_t dst = bBU + (uint32_t)(st * BSTAGE + n * 64 + ((q ^ (n & 3)) << 4));
        cp16(dst, src);
    }
    asm volatile("cp.async.commit_group;" ::: "memory");
}

// ---- prep: transpose + fp16 round + layer-0 channel remap -------------------
__global__ void prep_kernel(const float* __restrict__ W0, const float* __restrict__ W1,
                            const float* __restrict__ W2, const float* __restrict__ W3)
{
    int n = blockIdx.x;              // output channel
    int l = blockIdx.y;              // layer
    int k = threadIdx.x;             // NEW input channel k'
    float v = 0.f;
    if (l == 0) {
        int ks = (k < 13) ? k : ((k >= 16 && k < 208) ? k - 3 : -1);
        if (ks >= 0) v = __ldg(W0 + ks * HH + n);
    } else {
        const float* W = (l == 1) ? W1 : (l == 2) ? W2 : W3;
        v = __ldg(W + k * HH + n);
    }
    g_B16[l][n * HH + k] = __float2half(v);
}

// ---- main fused kernel ------------------------------------------------------
__global__ void __launch_bounds__(NTHR, 2)
lisa_mma(const float* __restrict__ coord, const float* __restrict__ latent,
         const float* __restrict__ b0, const float* __restrict__ b1,
         const float* __restrict__ b2, const float* __restrict__ b3,
         const float* __restrict__ W4, const float* __restrict__ b4,
         float* __restrict__ out, Sizes sz)
{
    extern __shared__ char sm[];
    const uint32_t sm0 = smem_u32(sm);
    const uint32_t aU = sm0, bBU = sm0 + OFF_B;

    const int t = threadIdx.x, wid = t >> 5, lane = t & 31;
    const int nw = wid;                      // N-slice warp (32 cols each)
    const int tok0 = blockIdx.x * MT;
    const int bb = tok0 / LLEN;
    const float* lat = latent + bb * NN * DD;

    // prefetch layer-0 panels 0..2 (overlaps the feature build below)
    issue_panel(bBU, 0, g_B16[0], 0, t);
    issue_panel(bBU, 1, g_B16[0], 1, t);
    issue_panel(bBU, 2, g_B16[0], 2, t);

    // ---- feature build (channel-remapped layout) ----------------------------
    // ch 0..12: coord|PE, 13..15: 0, 16..207: sampled (s*64+d), 208..223: 0
#pragma unroll 4
    for (int tt = 0; tt < 8; ++tt) {
        int m = wid * 8 + tt;                // 8 warps x 8 = 64 tokens
        float c = __ldg(coord + min(tok0 + m, sz.c - 1));
        float ix = c * (float)NN - 0.5f;
        float x0f = floorf(ix);
        float fr = ix - x0f, om = 1.f - fr;
        int x0 = (int)x0f;
        int i0 = min(max(x0, 0), NN - 1);
        int i1 = min(max(x0 + 1, 0), NN - 1);
        int off = (i1 > i0) ? 1 : 0;         // border-clamp exactness
        float2 rv[4];
#pragma unroll
        for (int j = 0; j < 4; ++j) {
            int rr = min(max(i0 - 1 + j, 0), NN - 1);
            rv[j] = __ldg(reinterpret_cast<const float2*>(lat + rr * DD + 2 * lane));
        }
#pragma unroll
        for (int s = 0; s < 3; ++s) {
            float2 f0 = rv[s], f1 = rv[s + off];
            float v0 = om * f0.x + fr * f1.x;
            float v1 = om * f0.y + fr * f1.y;
            *reinterpret_cast<uint32_t*>(sm + a_off(m, 16 + s * 64 + 2 * lane))
                = pack_h2(v0, v1);
        }
        float v = 0.f;
        if (lane == 0) v = c;
        else if (lane < 13) {
            int k = lane - 1;
            float ang = c * (float)(1 << (k >> 1));
            v = (k & 1) ? __cosf(ang) : __sinf(ang);
        }
        int chz = (lane < 16) ? lane : (192 + lane);     // 0..15 | 208..223
        *reinterpret_cast<__half*>(sm + a_off(m, chz)) = __float2half(v);
    }

    const float* bgs[4] = { b0, b1, b2, b3 };

#pragma unroll 1
    for (int l = 0; l < 4; ++l) {
        const int nP = (l == 0) ? 7 : 8;     // layer0 K=224

        float C[4][4][4];
#pragma unroll
        for (int a = 0; a < 4; ++a)
#pragma unroll
            for (int b = 0; b < 4; ++b)
#pragma unroll
                for (int q = 0; q < 4; ++q) C[a][b][q] = 0.f;

        // paired-panel mainloop: ONE sync per two panels
#pragma unroll 1
        for (int pp = 0; pp < nP; pp += 2) {
            if (pp + 2 >= nP) {
                asm volatile("cp.async.wait_group 0;" ::: "memory");
            } else {
                asm volatile("cp.async.wait_group 1;" ::: "memory");
            }
            __syncthreads();     // panels pp, pp+1 visible; stages of pp+3/pp+4
                                 // (== panels pp-2/pp-1) free; A writes ordered

            if (pp + 3 < nP) issue_panel(bBU, (pp + 3) % NSTG, g_B16[l], pp + 3, t);
            if (pp + 4 < nP) issue_panel(bBU, (pp + 4) % NSTG, g_B16[l], pp + 4, t);

#pragma unroll
            for (int pi = 0; pi < 2; ++pi) {
                const int p = pp + pi;
                if (p >= nP) break;
                const uint32_t bU = bBU + (uint32_t)((p % NSTG) * BSTAGE);
#pragma unroll
                for (int ks = 0; ks < 2; ++ks) {
                    uint32_t bh[4][2];
#pragma unroll
                    for (int nt = 0; nt < 4; ++nt) {
                        int row = nw * 32 + nt * 8 + (lane & 7);
                        int chk = 2 * ks + ((lane >> 3) & 1);
                        uint32_t rowb = bU + (uint32_t)(row * 64
                                                        + ((chk ^ (row & 3)) << 4));
                        ldsm2(bh[nt], rowb);
                    }
#pragma unroll
                    for (int mt = 0; mt < 4; ++mt) {
                        uint32_t ah[4];
                        int row = mt * 16 + (lane & 15);
                        int chk = p * 4 + ks * 2 + (lane >> 4);
                        uint32_t ra = aU + (uint32_t)(row * ASTRB
                                                      + ((chk ^ (row & 7)) << 4));
                        ldsm4(ah, ra);
#pragma unroll
                        for (int nt = 0; nt < 4; ++nt) mmah(C[mt][nt], ah, bh[nt]);
                    }
                }
            }
        }
        __syncthreads();         // all compute done: A writable, B stages free

        if (l < 3) {             // prefetch next layer's first panels over epilogue
            issue_panel(bBU, 0, g_B16[l + 1], 0, t);
            issue_panel(bBU, 1, g_B16[l + 1], 1, t);
            issue_panel(bBU, 2, g_B16[l + 1], 2, t);
        }

        const float* bg = bgs[l];
        if (l < 3) {
            // bias + relu + fp16 round into A (k-layout for next layer)
#pragma unroll
            for (int nt = 0; nt < 4; ++nt) {
                int n0 = nw * 32 + nt * 8 + (lane & 3) * 2;
                float bi0 = __ldg(bg + n0), bi1 = __ldg(bg + n0 + 1);
#pragma unroll
                for (int mt = 0; mt < 4; ++mt) {
                    int m0 = mt * 16 + (lane >> 2);
                    float v0 = fmaxf(C[mt][nt][0] + bi0, 0.f);
                    float v1 = fmaxf(C[mt][nt][1] + bi1, 0.f);
                    float v2 = fmaxf(C[mt][nt][2] + bi0, 0.f);
                    float v3 = fmaxf(C[mt][nt][3] + bi1, 0.f);
                    *reinterpret_cast<uint32_t*>(sm + a_off(m0, n0))     = pack_h2(v0, v1);
                    *reinterpret_cast<uint32_t*>(sm + a_off(m0 + 8, n0)) = pack_h2(v2, v3);
                }
            }
            // next layer's iter-0 sync orders these writes before ldmatrix
        } else {
            // final: bias+relu, dot with W4, reduce 256->1 per token
            float slo[4] = {0.f, 0.f, 0.f, 0.f}, shi[4] = {0.f, 0.f, 0.f, 0.f};
#pragma unroll
            for (int nt = 0; nt < 4; ++nt) {
                int n0 = nw * 32 + nt * 8 + (lane & 3) * 2;
                float bi0 = __ldg(bg + n0), bi1 = __ldg(bg + n0 + 1);
                float w0 = __ldg(W4 + n0), w1 = __ldg(W4 + n0 + 1);
#pragma unroll
                for (int mt = 0; mt < 4; ++mt) {
                    slo[mt] += fmaxf(C[mt][nt][0] + bi0, 0.f) * w0
                             + fmaxf(C[mt][nt][1] + bi1, 0.f) * w1;
                    shi[mt] += fmaxf(C[mt][nt][2] + bi0, 0.f) * w0
                             + fmaxf(C[mt][nt][3] + bi1, 0.f) * w1;
                }
            }
#pragma unroll
            for (int mt = 0; mt < 4; ++mt) {
                slo[mt] += __shfl_xor_sync(0xffffffffu, slo[mt], 1);
                slo[mt] += __shfl_xor_sync(0xffffffffu, slo[mt], 2);
                shi[mt] += __shfl_xor_sync(0xffffffffu, shi[mt], 1);
                shi[mt] += __shfl_xor_sync(0xffffffffu, shi[mt], 2);
            }
            float* red = reinterpret_cast<float*>(sm + OFF_B);   // 64 x 8 floats
            if ((lane & 3) == 0) {
                int g = lane >> 2;
#pragma unroll
                for (int mt = 0; mt < 4; ++mt) {
                    int m0 = mt * 16 + g;
                    red[m0 * 8 + nw]       = slo[mt];
                    red[(m0 + 8) * 8 + nw] = shi[mt];
                }
            }
            __syncthreads();
            if (t < MT) {
                float r = __ldg(b4);
#pragma unroll
                for (int ww = 0; ww < 8; ++ww) r += red[t * 8 + ww];
                if (tok0 + t < sz.outN) out[tok0 + t] = r;
            }
        }
    }
}

// ---- size-based input resolution (elements OR bytes; any ordering) ----------
extern "C" void kernel_launch(void* const* d_in, const int* in_sizes, int n_in,
                              void* d_out, int out_size) {
    long long es[64];
    int m = n_in > 64 ? 64 : n_in;
    bool bytemode = false;
    for (int i = 0; i < m; ++i) if (in_sizes[i] == 4194304) bytemode = true;
    for (int i = 0; i < m; ++i)
        es[i] = bytemode ? (long long)in_sizes[i] / 4 : (long long)in_sizes[i];
    long long outN = bytemode ? (long long)out_size / 4 : (long long)out_size;

    int iCoord = -1, iLat = -1, iW0 = -1, iB4 = -1;
    int idx65[3];  int n65 = 0;
    int idx256[5]; int n256 = 0;
    for (int i = 0; i < m; ++i) {
        long long s = es[i];
        if      (s == 262144)  iCoord = i;
        else if (s == 1048576) iLat   = i;
        else if (s == 52480)   iW0    = i;
        else if (s == 1)       iB4    = i;
        else if (s == 65536 && n65 < 3)  idx65[n65++]  = i;
        else if (s == 256   && n256 < 5) idx256[n256++] = i;
    }

    int iW1, iW2, iW3, iW4, iB0, iB1, iB2, iB3;
    if (n65 == 3 && n256 == 5 && iCoord >= 0 && iLat >= 0 && iW0 >= 0 && iB4 >= 0) {
        iW1 = idx65[0]; iW2 = idx65[1]; iW3 = idx65[2];
        if (idx256[0] < idx65[0]) {     // biases interleaved (declaration order)
            iB0 = idx256[0]; iB1 = idx256[1]; iB2 = idx256[2];
            iB3 = idx256[3]; iW4 = idx256[4];
        } else {                        // W-block first (sorted order)
            iW4 = idx256[0]; iB0 = idx256[1]; iB1 = idx256[2];
            iB2 = idx256[3]; iB3 = idx256[4];
        }
    } else {
        iCoord = 0 % m;  iLat = 1 % m;  iW0 = 2 % m;  iB0 = 3 % m;
        iW1 = 4 % m;     iB1 = 5 % m;   iW2 = 6 % m;  iB2 = 7 % m;
        iW3 = 8 % m;     iB3 = 9 % m;   iW4 = 10 % m; iB4 = 11 % m;
    }

    Sizes sz;
    sz.c = (int)es[iCoord]; sz.outN = (int)outN;

    const float* coord  = (const float*)d_in[iCoord];
    const float* latent = (const float*)d_in[iLat];
    const float* W0 = (const float*)d_in[iW0]; const float* b0 = (const float*)d_in[iB0];
    const float* W1 = (const float*)d_in[iW1]; const float* b1 = (const float*)d_in[iB1];
    const float* W2 = (const float*)d_in[iW2]; const float* b2 = (const float*)d_in[iB2];
    const float* W3 = (const float*)d_in[iW3]; const float* b3 = (const float*)d_in[iB3];
    const float* W4 = (const float*)d_in[iW4]; const float* b4 = (const float*)d_in[iB4];

    prep_kernel<<<dim3(HH, 4), HH>>>(W0, W1, W2, W3);

    cudaFuncSetAttribute(lisa_mma, cudaFuncAttributeMaxDynamicSharedMemorySize,
                         SMEM_DYN);
    int blocks = (int)((outN + MT - 1) / MT);    // 4096 expected
    lisa_mma<<<blocks, NTHR, SMEM_DYN>>>(coord, latent, b0, b1, b2, b3, W4, b4,
                                         (float*)d_out, sz);
}